// round 1
// baseline (speedup 1.0000x reference)
#include <cuda_runtime.h>
#include <cstdint>

#define NP 4096
#define BB 2

// ---------------- scratch (static device globals; no allocation) ----------------
__device__ float g_c1[BB*128*NP];                 // conv1 out
__device__ float g_h0[BB*128*NP];                 // conv2 out (SA layer-0 input)
__device__ float g_q [BB*32*NP];
__device__ float g_v [BB*128*NP];
__device__ float g_u [BB*128*NP];                 // h - x_r
__device__ float g_attn[(size_t)BB*NP*NP];        // 134 MB
__device__ float g_colsum[BB*NP];
__device__ float g_feats[BB*512*NP];
__device__ float g_hf[BB*1024*NP];
__device__ float g_xmax[BB*1024];
__device__ float g_xavg[BB*1024];
__device__ float g_r1[BB*512];
__device__ float g_s1[BB*512*NP];
__device__ float g_s2[BB*256*NP];

// ---------------- generic tiled SGEMM with fused epilogues ----------------
// C[b] = epilogue( A[b] * B[b] )
// A: MxK (row-major, leading dim lda). If TA: logical A[m,k] = Aptr[k*lda + m].
// B: KxN row-major. N assumed %64==0, K assumed %16==0. M guarded.
// Epilogue order: (COLDIV) v = acc/(1e-9+cs[n]); v = (v + rowbias[m])*scale[m]+shift[m];
//                 ACT (1=relu, 2=leaky(slope)); RES (1: res+v, 2: res-v).
template<bool TA, int ACT, int RES, bool COLDIV>
__global__ void gemm_k(int M, int N, int K, int lda,
    const float* __restrict__ A, size_t sA,
    const float* __restrict__ B, size_t sB,
    float* __restrict__ C, size_t sC,
    const float* __restrict__ rb, size_t sRB,
    const float* __restrict__ bng, const float* __restrict__ bnb, float bninv,
    const float* __restrict__ res, size_t sRes,
    const float* __restrict__ cs, size_t sCS,
    float slope)
{
    __shared__ float As[16][68];
    __shared__ float Bs[16][68];
    const int b  = blockIdx.z;
    const float* Ab = A + (size_t)b * sA;
    const float* Bb = B + (size_t)b * sB;
    const int m0 = blockIdx.y * 64;
    const int n0 = blockIdx.x * 64;
    const int tid = threadIdx.x;
    const int tx = tid & 15, ty = tid >> 4;

    float acc[4][4];
    #pragma unroll
    for (int i = 0; i < 4; i++)
        #pragma unroll
        for (int j = 0; j < 4; j++) acc[i][j] = 0.f;

    for (int k0 = 0; k0 < K; k0 += 16) {
        if (TA) {
            int kk = tid >> 4, mq = tid & 15;
            float4 av = *(const float4*)&Ab[(size_t)(k0 + kk) * lda + m0 + mq * 4];
            *(float4*)&As[kk][mq * 4] = av;
        } else {
            int m = tid >> 2, kq = tid & 3;
            float4 av = make_float4(0.f, 0.f, 0.f, 0.f);
            if (m0 + m < M)
                av = *(const float4*)&Ab[(size_t)(m0 + m) * lda + k0 + kq * 4];
            As[kq * 4 + 0][m] = av.x;
            As[kq * 4 + 1][m] = av.y;
            As[kq * 4 + 2][m] = av.z;
            As[kq * 4 + 3][m] = av.w;
        }
        {
            int kk = tid >> 4, nq = tid & 15;
            float4 bv = *(const float4*)&Bb[(size_t)(k0 + kk) * N + n0 + nq * 4];
            *(float4*)&Bs[kk][nq * 4] = bv;
        }
        __syncthreads();
        #pragma unroll
        for (int k = 0; k < 16; k++) {
            float4 a4 = *(float4*)&As[k][ty * 4];
            float4 b4 = *(float4*)&Bs[k][tx * 4];
            float ar[4] = {a4.x, a4.y, a4.z, a4.w};
            float br[4] = {b4.x, b4.y, b4.z, b4.w};
            #pragma unroll
            for (int i = 0; i < 4; i++)
                #pragma unroll
                for (int j = 0; j < 4; j++)
                    acc[i][j] = fmaf(ar[i], br[j], acc[i][j]);
        }
        __syncthreads();
    }

    #pragma unroll
    for (int i = 0; i < 4; i++) {
        int m = m0 + ty * 4 + i;
        if (m >= M) continue;
        float scale = (bng ? bng[m] : 1.f) * bninv;
        float shift = bnb ? bnb[m] : 0.f;
        float rbv   = rb  ? rb[(size_t)b * sRB + m] : 0.f;
        #pragma unroll
        for (int j = 0; j < 4; j++) {
            int n = n0 + tx * 4 + j;
            float v = acc[i][j];
            if (COLDIV) v = v / (1e-9f + cs[(size_t)b * sCS + n]);
            v = (v + rbv) * scale + shift;
            if (ACT == 1) v = fmaxf(v, 0.f);
            else if (ACT == 2) v = v > 0.f ? v : slope * v;
            if (RES == 1)      v = res[(size_t)b * sRes + (size_t)m * N + n] + v;
            else if (RES == 2) v = res[(size_t)b * sRes + (size_t)m * N + n] - v;
            C[(size_t)b * sC + (size_t)m * N + n] = v;
        }
    }
}

// ---------------- conv1: 3->128 channels, bn+relu ----------------
__global__ void conv1_k(const float* __restrict__ x, const float* __restrict__ w1,
                        const float* __restrict__ g, const float* __restrict__ bb,
                        float inv, float* __restrict__ out)
{
    int idx = blockIdx.x * blockDim.x + threadIdx.x;   // B*128*NP
    int n = idx & (NP - 1);
    int o = (idx / NP) & 127;
    int b = idx / (128 * NP);
    const float* xp = x + ((size_t)b * 15 + 9) * NP + n;
    float s = w1[o * 3 + 0] * xp[0] + w1[o * 3 + 1] * xp[NP] + w1[o * 3 + 2] * xp[2 * NP];
    s = s * g[o] * inv + bb[o];
    out[idx] = fmaxf(s, 0.f);
}

// ---------------- row softmax (4096-wide rows, in place) ----------------
__global__ void softmax_rows(float* __restrict__ attn)
{
    size_t row = blockIdx.x;                 // B*NP rows
    float* p = attn + row * NP;
    int t = threadIdx.x;                      // 256 threads, 16 elems each
    float vals[16];
    float m = -1e30f;
    #pragma unroll
    for (int i = 0; i < 16; i++) { vals[i] = p[t + i * 256]; m = fmaxf(m, vals[i]); }
    __shared__ float red[256];
    red[t] = m; __syncthreads();
    for (int s = 128; s > 0; s >>= 1) { if (t < s) red[t] = fmaxf(red[t], red[t + s]); __syncthreads(); }
    m = red[0]; __syncthreads();
    float sum = 0.f;
    #pragma unroll
    for (int i = 0; i < 16; i++) { vals[i] = __expf(vals[i] - m); sum += vals[i]; }
    red[t] = sum; __syncthreads();
    for (int s = 128; s > 0; s >>= 1) { if (t < s) red[t] += red[t + s]; __syncthreads(); }
    float invs = 1.f / red[0];
    #pragma unroll
    for (int i = 0; i < 16; i++) p[t + i * 256] = vals[i] * invs;
}

// ---------------- column sums of attn ----------------
__global__ void colsum_k(const float* __restrict__ attn, float* __restrict__ cs)
{
    int j = blockIdx.x * blockDim.x + threadIdx.x;     // B*NP
    int b = j / NP, jj = j & (NP - 1);
    const float* p = attn + (size_t)b * NP * NP + jj;
    float s = 0.f;
    #pragma unroll 8
    for (int i = 0; i < NP; i++) s += p[(size_t)i * NP];
    cs[j] = s;
}

// ---------------- global max/mean pooling over N ----------------
__global__ void pool_k(const float* __restrict__ hf, float* __restrict__ xmax, float* __restrict__ xavg)
{
    int bc = blockIdx.x;                       // B*1024
    const float* p = hf + (size_t)bc * NP;
    int t = threadIdx.x;
    float mx = -1e30f, sm = 0.f;
    for (int i = t; i < NP; i += 256) { float v = p[i]; mx = fmaxf(mx, v); sm += v; }
    __shared__ float rm[256], rs[256];
    rm[t] = mx; rs[t] = sm; __syncthreads();
    for (int s = 128; s > 0; s >>= 1) {
        if (t < s) { rm[t] = fmaxf(rm[t], rm[t + s]); rs[t] += rs[t + s]; }
        __syncthreads();
    }
    if (t == 0) { xmax[bc] = rm[0]; xavg[bc] = rs[0] * (1.f / NP); }
}

// ---------------- fold pooled channels of ws1 into per-row bias ----------------
__global__ void r1_k(const float* __restrict__ ws1, const float* __restrict__ bs1,
                     const float* __restrict__ xmax, const float* __restrict__ xavg,
                     float* __restrict__ r1)
{
    int idx = blockIdx.x * blockDim.x + threadIdx.x;   // B*512
    if (idx >= BB * 512) return;
    int b = idx / 512, o = idx % 512;
    const float* w = ws1 + (size_t)o * 3072;
    float s = bs1[o];
    #pragma unroll 4
    for (int c = 0; c < 1024; c++)
        s += w[1024 + c] * xmax[b * 1024 + c] + w[2048 + c] * xavg[b * 1024 + c];
    r1[idx] = s;
}

// ---------------- ws3 (8x256) + log_softmax + transpose ----------------
__global__ void final_k(const float* __restrict__ s2, const float* __restrict__ ws3,
                        const float* __restrict__ bs3, float* __restrict__ out)
{
    __shared__ float w[8 * 256];
    __shared__ float bias[8];
    int t = threadIdx.x;
    for (int i = t; i < 2048; i += blockDim.x) w[i] = ws3[i];
    if (t < 8) bias[t] = bs3[t];
    __syncthreads();
    int idx = blockIdx.x * blockDim.x + t;    // B*NP
    int b = idx / NP, n = idx & (NP - 1);
    const float* sp = s2 + (size_t)b * 256 * NP + n;
    float l[8];
    #pragma unroll
    for (int k = 0; k < 8; k++) l[k] = bias[k];
    for (int c = 0; c < 256; c++) {
        float v = sp[(size_t)c * NP];
        #pragma unroll
        for (int k = 0; k < 8; k++) l[k] = fmaf(w[k * 256 + c], v, l[k]);
    }
    float m = l[0];
    #pragma unroll
    for (int k = 1; k < 8; k++) m = fmaxf(m, l[k]);
    float s = 0.f;
    #pragma unroll
    for (int k = 0; k < 8; k++) s += expf(l[k] - m);
    float lse = m + logf(s);
    #pragma unroll
    for (int k = 0; k < 8; k++)
        out[((size_t)b * NP + n) * 8 + k] = l[k] - lse;
}

// ---------------- host launch ----------------
extern "C" void kernel_launch(void* const* d_in, const int* in_sizes, int n_in,
                              void* d_out, int out_size)
{
    const float* x      = (const float*)d_in[0];
    const float* w1     = (const float*)d_in[1];
    const float* bn1_g  = (const float*)d_in[2];
    const float* bn1_b  = (const float*)d_in[3];
    const float* w2     = (const float*)d_in[4];
    const float* bn2_g  = (const float*)d_in[5];
    const float* bn2_b  = (const float*)d_in[6];
    const float* sa_wqk = (const float*)d_in[7];
    const float* sa_wv  = (const float*)d_in[8];
    const float* sa_bv  = (const float*)d_in[9];
    const float* sa_wt  = (const float*)d_in[10];
    const float* sa_bt  = (const float*)d_in[11];
    const float* sa_bng = (const float*)d_in[12];
    const float* sa_bnb = (const float*)d_in[13];
    const float* wf     = (const float*)d_in[14];
    const float* bnf_g  = (const float*)d_in[15];
    const float* bnf_b  = (const float*)d_in[16];
    const float* ws1    = (const float*)d_in[17];
    const float* bs1    = (const float*)d_in[18];
    const float* bns1_g = (const float*)d_in[19];
    const float* bns1_b = (const float*)d_in[20];
    const float* ws2    = (const float*)d_in[21];
    const float* bs2    = (const float*)d_in[22];
    const float* bns2_g = (const float*)d_in[23];
    const float* bns2_b = (const float*)d_in[24];
    const float* ws3    = (const float*)d_in[25];
    const float* bs3    = (const float*)d_in[26];
    float* out = (float*)d_out;

    float *c1, *h0, *q, *v, *u, *attn, *colsum, *feats, *hf, *xmax, *xavg, *r1, *s1, *s2;
    cudaGetSymbolAddress((void**)&c1,     g_c1);
    cudaGetSymbolAddress((void**)&h0,     g_h0);
    cudaGetSymbolAddress((void**)&q,      g_q);
    cudaGetSymbolAddress((void**)&v,      g_v);
    cudaGetSymbolAddress((void**)&u,      g_u);
    cudaGetSymbolAddress((void**)&attn,   g_attn);
    cudaGetSymbolAddress((void**)&colsum, g_colsum);
    cudaGetSymbolAddress((void**)&feats,  g_feats);
    cudaGetSymbolAddress((void**)&hf,     g_hf);
    cudaGetSymbolAddress((void**)&xmax,   g_xmax);
    cudaGetSymbolAddress((void**)&xavg,   g_xavg);
    cudaGetSymbolAddress((void**)&r1,     g_r1);
    cudaGetSymbolAddress((void**)&s1,     g_s1);
    cudaGetSymbolAddress((void**)&s2,     g_s2);

    const float INV = 0.999995000037499219f;   // 1/sqrt(1 + 1e-5)
    const size_t AT = (size_t)NP * NP;         // attn per-batch stride
    dim3 blk(256);

    // conv1: 3 -> 128, bn+relu
    conv1_k<<<(BB * 128 * NP) / 256, blk>>>(x, w1, bn1_g, bn1_b, INV, c1);

    // conv2: 128 -> 128, bn+relu
    gemm_k<false,1,0,false><<<dim3(NP/64, 2, BB), blk>>>(128, NP, 128, 128,
        w2, 0, c1, (size_t)128*NP, h0, (size_t)128*NP,
        nullptr, 0, bn2_g, bn2_b, INV, nullptr, 0, nullptr, 0, 0.f);

    for (int i = 0; i < 4; i++) {
        const float* hin = (i == 0) ? h0 : feats + (size_t)(i - 1) * 128 * NP;
        size_t sHin = (i == 0) ? (size_t)128 * NP : (size_t)512 * NP;

        // q = wqk @ h  (32 x 4096)
        gemm_k<false,0,0,false><<<dim3(NP/64, 1, BB), blk>>>(32, NP, 128, 128,
            sa_wqk + (size_t)i*32*128, 0, hin, sHin, q, (size_t)32*NP,
            nullptr, 0, nullptr, nullptr, 1.f, nullptr, 0, nullptr, 0, 0.f);

        // energy = q^T q  (4096 x 4096)
        gemm_k<true,0,0,false><<<dim3(NP/64, NP/64, BB), blk>>>(NP, NP, 32, NP,
            q, (size_t)32*NP, q, (size_t)32*NP, attn, AT,
            nullptr, 0, nullptr, nullptr, 1.f, nullptr, 0, nullptr, 0, 0.f);

        softmax_rows<<<BB * NP, blk>>>(attn);
        colsum_k<<<(BB * NP) / 256, blk>>>(attn, colsum);

        // v = wv @ h + bv
        gemm_k<false,0,0,false><<<dim3(NP/64, 2, BB), blk>>>(128, NP, 128, 128,
            sa_wv + (size_t)i*128*128, 0, hin, sHin, v, (size_t)128*NP,
            sa_bv + (size_t)i*128, 0, nullptr, nullptr, 1.f, nullptr, 0, nullptr, 0, 0.f);

        // u = h - (v @ attn) / (1e-9 + colsum)
        gemm_k<false,0,2,true><<<dim3(NP/64, 2, BB), blk>>>(128, NP, NP, NP,
            v, (size_t)128*NP, attn, AT, u, (size_t)128*NP,
            nullptr, 0, nullptr, nullptr, 1.f, hin, sHin, colsum, (size_t)NP, 0.f);

        // h_new = h + relu(bn(wt @ u + bt))  -> feats block i
        gemm_k<false,1,1,false><<<dim3(NP/64, 2, BB), blk>>>(128, NP, 128, 128,
            sa_wt + (size_t)i*128*128, 0, u, (size_t)128*NP,
            feats + (size_t)i*128*NP, (size_t)512*NP,
            sa_bt + (size_t)i*128, 0, sa_bng + (size_t)i*128, sa_bnb + (size_t)i*128, INV,
            hin, sHin, nullptr, 0, 0.f);
    }

    // wf: 512 -> 1024, bn + leaky_relu(0.2)
    gemm_k<false,2,0,false><<<dim3(NP/64, 16, BB), blk>>>(1024, NP, 512, 512,
        wf, 0, feats, (size_t)512*NP, hf, (size_t)1024*NP,
        nullptr, 0, bnf_g, bnf_b, INV, nullptr, 0, nullptr, 0, 0.2f);

    pool_k<<<BB * 1024, blk>>>(hf, xmax, xavg);
    r1_k<<<(BB * 512 + 255) / 256, blk>>>(ws1, bs1, xmax, xavg, r1);

    // ws1 (first 1024 input channels; pooled part folded into r1), bn + relu
    gemm_k<false,1,0,false><<<dim3(NP/64, 8, BB), blk>>>(512, NP, 1024, 3072,
        ws1, 0, hf, (size_t)1024*NP, s1, (size_t)512*NP,
        r1, 512, bns1_g, bns1_b, INV, nullptr, 0, nullptr, 0, 0.f);

    // ws2: 512 -> 256, bn + relu
    gemm_k<false,1,0,false><<<dim3(NP/64, 4, BB), blk>>>(256, NP, 512, 512,
        ws2, 0, s1, (size_t)512*NP, s2, (size_t)256*NP,
        bs2, 0, bns2_g, bns2_b, INV, nullptr, 0, nullptr, 0, 0.f);

    // ws3 + log_softmax + transpose
    final_k<<<(BB * NP) / 256, blk>>>(s2, ws3, bs3, out);
}

// round 4
// speedup vs baseline: 1.2633x; 1.2633x over previous
#include <cuda_runtime.h>
#include <cstdint>

#define NP 4096
#define BB 2

// ---------------- scratch (static device globals; no allocation) ----------------
__device__ float g_c1[BB*128*NP];
__device__ float g_h0[BB*128*NP];
__device__ float g_q [BB*32*NP];
__device__ float g_v [BB*128*NP];
__device__ float g_u [BB*128*NP];
__device__ float g_attn[(size_t)BB*NP*NP];        // 134 MB
__device__ float g_colsum[BB*NP];
__device__ float g_feats[BB*512*NP];
__device__ float g_hf[BB*1024*NP];
__device__ float g_xmax[BB*1024];
__device__ float g_xavg[BB*1024];
__device__ float g_r1[BB*512];
__device__ float g_s1[BB*512*NP];
__device__ float g_s2[BB*256*NP];

// ---------------- PTX helpers ----------------
__device__ __forceinline__ uint32_t smem_u32(const void* p) {
    return (uint32_t)__cvta_generic_to_shared(p);
}
__device__ __forceinline__ void cpa16(uint32_t s, const void* g) {
    asm volatile("cp.async.cg.shared.global [%0], [%1], 16;" :: "r"(s), "l"(g));
}
__device__ __forceinline__ void cpa_commit() { asm volatile("cp.async.commit_group;"); }
__device__ __forceinline__ void cpa_wait0()  { asm volatile("cp.async.wait_group 0;"); }
__device__ __forceinline__ uint32_t f2tf(float f) {
    uint32_t r;
    asm("cvt.rna.tf32.f32 %0, %1;" : "=r"(r) : "f"(f));
    return r;
}
__device__ __forceinline__ void mma_tf32(float* c, const uint32_t* a, const uint32_t* b) {
    asm volatile(
        "mma.sync.aligned.m16n8k8.row.col.f32.tf32.tf32.f32 "
        "{%0,%1,%2,%3}, {%4,%5,%6,%7}, {%8,%9}, {%0,%1,%2,%3};"
        : "+f"(c[0]), "+f"(c[1]), "+f"(c[2]), "+f"(c[3])
        : "r"(a[0]), "r"(a[1]), "r"(a[2]), "r"(a[3]), "r"(b[0]), "r"(b[1]));
}

// ---------------- tf32 tensor-core GEMM with fused epilogues ----------------
// C = epi(A @ B); A: MxK fp32 row-major (leading dim lda), B: KxN fp32 row-major.
// BM=128, BK=16. M%128==0, N%BN==0, K%16==0 required. All storage fp32.
template<int BN>
__device__ __forceinline__ void t_load(float* As, float* Bs,
    const float* __restrict__ Ab, const float* __restrict__ Bb,
    int tid, int kt, int lda, int N)
{
    constexpr int ASTR = 20;
    constexpr int BSTR = BN + 8;
    #pragma unroll
    for (int i = 0; i < 2; i++) {
        int idx = tid + i * 256;                 // 512 float4 for A (128x16)
        int row = idx >> 2, seg = (idx & 3) * 4;
        cpa16(smem_u32(As + row * ASTR + seg), Ab + (size_t)row * lda + kt * 16 + seg);
    }
    constexpr int BF4 = BN / 64;                 // 16*BN/4 float4 / 256 threads
    #pragma unroll
    for (int i = 0; i < BF4; i++) {
        int idx = tid + i * 256;
        int row = idx / (BN / 4), seg = (idx % (BN / 4)) * 4;
        cpa16(smem_u32(Bs + row * BSTR + seg), Bb + (size_t)(kt * 16 + row) * N + seg);
    }
}

template<int BN, int ACT, int RES, bool COLDIV>
__global__ __launch_bounds__(256) void tgemm_k(int M, int N, int K, int lda,
    const float* __restrict__ A, size_t sA,
    const float* __restrict__ B, size_t sB,
    float* __restrict__ C, size_t sC,
    const float* __restrict__ rb, size_t sRB,
    const float* __restrict__ bng, const float* __restrict__ bnb, float bninv,
    const float* __restrict__ res, size_t sRes,
    const float* __restrict__ cs, size_t sCS,
    float slope)
{
    constexpr int BM = 128, BK = 16;
    constexpr int ASTR = 20;                 // conflict-free: 20r%32 distinct over r%8
    constexpr int BSTR = BN + 8;             // ≡8 mod 32 -> 8r+c distinct
    constexpr int WN = BN / 4;
    constexpr int NT = WN / 8;
    __shared__ __align__(16) float As[2][BM * ASTR];
    __shared__ __align__(16) float Bs[2][BK * BSTR];

    const int b = blockIdx.z;
    const int m0 = blockIdx.y * BM, n0 = blockIdx.x * BN;
    const float* Ab = A + (size_t)b * sA + (size_t)m0 * lda;
    const float* Bb = B + (size_t)b * sB + n0;
    const int tid = threadIdx.x;
    const int wid = tid >> 5, lane = tid & 31;
    const int wm = wid >> 2, wn = wid & 3;   // 2 x 4 warp grid (64 x WN per warp)
    const int lr = lane >> 2, lc = lane & 3;

    float acc[4][NT][4];
    #pragma unroll
    for (int i = 0; i < 4; i++)
        #pragma unroll
        for (int j = 0; j < NT; j++)
            #pragma unroll
            for (int e = 0; e < 4; e++) acc[i][j][e] = 0.f;

    const int nk = K / BK;
    t_load<BN>(As[0], Bs[0], Ab, Bb, tid, 0, lda, N);
    cpa_commit();

    for (int kt = 0; kt < nk; kt++) {
        cpa_wait0();
        __syncthreads();
        int buf = kt & 1;
        if (kt + 1 < nk) {
            t_load<BN>(As[buf ^ 1], Bs[buf ^ 1], Ab, Bb, tid, kt + 1, lda, N);
            cpa_commit();
        }
        #pragma unroll
        for (int ks = 0; ks < 2; ks++) {
            const float* Ap = &As[buf][0];
            const float* Bp = &Bs[buf][0];
            uint32_t af[4][4];
            #pragma unroll
            for (int mt = 0; mt < 4; mt++) {
                int r = wm * 64 + mt * 16 + lr;
                int c = ks * 8 + lc;
                af[mt][0] = f2tf(Ap[(r    ) * ASTR + c    ]);
                af[mt][1] = f2tf(Ap[(r + 8) * ASTR + c    ]);
                af[mt][2] = f2tf(Ap[(r    ) * ASTR + c + 4]);
                af[mt][3] = f2tf(Ap[(r + 8) * ASTR + c + 4]);
            }
            uint32_t bf[NT][2];
            #pragma unroll
            for (int nt = 0; nt < NT; nt++) {
                int cgl = wn * WN + nt * 8 + lr;
                int k = ks * 8 + lc;
                bf[nt][0] = f2tf(Bp[(k    ) * BSTR + cgl]);
                bf[nt][1] = f2tf(Bp[(k + 4) * BSTR + cgl]);
            }
            #pragma unroll
            for (int mt = 0; mt < 4; mt++)
                #pragma unroll
                for (int nt = 0; nt < NT; nt++)
                    mma_tf32(acc[mt][nt], af[mt], bf[nt]);
        }
        __syncthreads();
    }

    // epilogue
    #pragma unroll
    for (int mt = 0; mt < 4; mt++) {
        #pragma unroll
        for (int h = 0; h < 2; h++) {
            int mm = m0 + wm * 64 + mt * 16 + h * 8 + lr;
            float scale = (bng ? bng[mm] : 1.f) * bninv;
            float shift = bnb ? bnb[mm] : 0.f;
            float rbv   = rb  ? rb[(size_t)b * sRB + mm] : 0.f;
            #pragma unroll
            for (int nt = 0; nt < NT; nt++) {
                int n = n0 + wn * WN + nt * 8 + lc * 2;
                float v0 = acc[mt][nt][h * 2 + 0];
                float v1 = acc[mt][nt][h * 2 + 1];
                if (COLDIV) {
                    v0 = v0 / (1e-9f + cs[(size_t)b * sCS + n]);
                    v1 = v1 / (1e-9f + cs[(size_t)b * sCS + n + 1]);
                }
                v0 = (v0 + rbv) * scale + shift;
                v1 = (v1 + rbv) * scale + shift;
                if (ACT == 1) { v0 = fmaxf(v0, 0.f); v1 = fmaxf(v1, 0.f); }
                else if (ACT == 2) { v0 = v0 > 0.f ? v0 : slope * v0; v1 = v1 > 0.f ? v1 : slope * v1; }
                if (RES == 1) {
                    v0 = res[(size_t)b * sRes + (size_t)mm * N + n] + v0;
                    v1 = res[(size_t)b * sRes + (size_t)mm * N + n + 1] + v1;
                } else if (RES == 2) {
                    v0 = res[(size_t)b * sRes + (size_t)mm * N + n] - v0;
                    v1 = res[(size_t)b * sRes + (size_t)mm * N + n + 1] - v1;
                }
                *(float2*)&C[(size_t)b * sC + (size_t)mm * N + n] = make_float2(v0, v1);
            }
        }
    }
}

// ---------------- fp32 tiled SGEMM with fused epilogues (small GEMMs) ----------------
template<bool TA, int ACT, int RES, bool COLDIV>
__global__ void gemm_k(int M, int N, int K, int lda,
    const float* __restrict__ A, size_t sA,
    const float* __restrict__ B, size_t sB,
    float* __restrict__ C, size_t sC,
    const float* __restrict__ rb, size_t sRB,
    const float* __restrict__ bng, const float* __restrict__ bnb, float bninv,
    const float* __restrict__ res, size_t sRes,
    const float* __restrict__ cs, size_t sCS,
    float slope)
{
    __shared__ float As[16][68];
    __shared__ float Bs[16][68];
    const int b  = blockIdx.z;
    const float* Ab = A + (size_t)b * sA;
    const float* Bb = B + (size_t)b * sB;
    const int m0 = blockIdx.y * 64;
    const int n0 = blockIdx.x * 64;
    const int tid = threadIdx.x;
    const int tx = tid & 15, ty = tid >> 4;

    float acc[4][4];
    #pragma unroll
    for (int i = 0; i < 4; i++)
        #pragma unroll
        for (int j = 0; j < 4; j++) acc[i][j] = 0.f;

    for (int k0 = 0; k0 < K; k0 += 16) {
        if (TA) {
            int kk = tid >> 4, mq = tid & 15;
            float4 av = *(const float4*)&Ab[(size_t)(k0 + kk) * lda + m0 + mq * 4];
            *(float4*)&As[kk][mq * 4] = av;
        } else {
            int m = tid >> 2, kq = tid & 3;
            float4 av = make_float4(0.f, 0.f, 0.f, 0.f);
            if (m0 + m < M)
                av = *(const float4*)&Ab[(size_t)(m0 + m) * lda + k0 + kq * 4];
            As[kq * 4 + 0][m] = av.x;
            As[kq * 4 + 1][m] = av.y;
            As[kq * 4 + 2][m] = av.z;
            As[kq * 4 + 3][m] = av.w;
        }
        {
            int kk = tid >> 4, nq = tid & 15;
            float4 bv = *(const float4*)&Bb[(size_t)(k0 + kk) * N + n0 + nq * 4];
            *(float4*)&Bs[kk][nq * 4] = bv;
        }
        __syncthreads();
        #pragma unroll
        for (int k = 0; k < 16; k++) {
            float4 a4 = *(float4*)&As[k][ty * 4];
            float4 b4 = *(float4*)&Bs[k][tx * 4];
            float ar[4] = {a4.x, a4.y, a4.z, a4.w};
            float br[4] = {b4.x, b4.y, b4.z, b4.w};
            #pragma unroll
            for (int i = 0; i < 4; i++)
                #pragma unroll
                for (int j = 0; j < 4; j++)
                    acc[i][j] = fmaf(ar[i], br[j], acc[i][j]);
        }
        __syncthreads();
    }

    #pragma unroll
    for (int i = 0; i < 4; i++) {
        int m = m0 + ty * 4 + i;
        if (m >= M) continue;
        float scale = (bng ? bng[m] : 1.f) * bninv;
        float shift = bnb ? bnb[m] : 0.f;
        float rbv   = rb  ? rb[(size_t)b * sRB + m] : 0.f;
        #pragma unroll
        for (int j = 0; j < 4; j++) {
            int n = n0 + tx * 4 + j;
            float v = acc[i][j];
            if (COLDIV) v = v / (1e-9f + cs[(size_t)b * sCS + n]);
            v = (v + rbv) * scale + shift;
            if (ACT == 1) v = fmaxf(v, 0.f);
            else if (ACT == 2) v = v > 0.f ? v : slope * v;
            if (RES == 1)      v = res[(size_t)b * sRes + (size_t)m * N + n] + v;
            else if (RES == 2) v = res[(size_t)b * sRes + (size_t)m * N + n] - v;
            C[(size_t)b * sC + (size_t)m * N + n] = v;
        }
    }
}

// ---------------- conv1 ----------------
__global__ void conv1_k(const float* __restrict__ x, const float* __restrict__ w1,
                        const float* __restrict__ g, const float* __restrict__ bb,
                        float inv, float* __restrict__ out)
{
    int idx = blockIdx.x * blockDim.x + threadIdx.x;
    int n = idx & (NP - 1);
    int o = (idx / NP) & 127;
    int b = idx / (128 * NP);
    const float* xp = x + ((size_t)b * 15 + 9) * NP + n;
    float s = w1[o * 3 + 0] * xp[0] + w1[o * 3 + 1] * xp[NP] + w1[o * 3 + 2] * xp[2 * NP];
    s = s * g[o] * inv + bb[o];
    out[idx] = fmaxf(s, 0.f);
}

// ---------------- row softmax (in place) ----------------
__global__ void softmax_rows(float* __restrict__ attn)
{
    size_t row = blockIdx.x;
    float* p = attn + row * NP;
    int t = threadIdx.x;
    float vals[16];
    float m = -1e30f;
    #pragma unroll
    for (int i = 0; i < 16; i++) { vals[i] = p[t + i * 256]; m = fmaxf(m, vals[i]); }
    __shared__ float red[256];
    red[t] = m; __syncthreads();
    for (int s = 128; s > 0; s >>= 1) { if (t < s) red[t] = fmaxf(red[t], red[t + s]); __syncthreads(); }
    m = red[0]; __syncthreads();
    float sum = 0.f;
    #pragma unroll
    for (int i = 0; i < 16; i++) { vals[i] = __expf(vals[i] - m); sum += vals[i]; }
    red[t] = sum; __syncthreads();
    for (int s = 128; s > 0; s >>= 1) { if (t < s) red[t] += red[t + s]; __syncthreads(); }
    float invs = 1.f / red[0];
    #pragma unroll
    for (int i = 0; i < 16; i++) p[t + i * 256] = vals[i] * invs;
}

// ---------------- column sums of attn ----------------
__global__ void colsum_k(const float* __restrict__ attn, float* __restrict__ cs)
{
    int j = blockIdx.x * blockDim.x + threadIdx.x;
    int b = j / NP, jj = j & (NP - 1);
    const float* p = attn + (size_t)b * NP * NP + jj;
    float s = 0.f;
    #pragma unroll 8
    for (int i = 0; i < NP; i++) s += p[(size_t)i * NP];
    cs[j] = s;
}

// ---------------- global max/mean pooling over N ----------------
__global__ void pool_k(const float* __restrict__ hf, float* __restrict__ xmax, float* __restrict__ xavg)
{
    int bc = blockIdx.x;
    const float* p = hf + (size_t)bc * NP;
    int t = threadIdx.x;
    float mx = -1e30f, sm = 0.f;
    for (int i = t; i < NP; i += 256) { float v = p[i]; mx = fmaxf(mx, v); sm += v; }
    __shared__ float rm[256], rs[256];
    rm[t] = mx; rs[t] = sm; __syncthreads();
    for (int s = 128; s > 0; s >>= 1) {
        if (t < s) { rm[t] = fmaxf(rm[t], rm[t + s]); rs[t] += rs[t + s]; }
        __syncthreads();
    }
    if (t == 0) { xmax[bc] = rm[0]; xavg[bc] = rs[0] * (1.f / NP); }
}

// ---------------- fold pooled channels of ws1 into per-row bias ----------------
__global__ void r1_k(const float* __restrict__ ws1, const float* __restrict__ bs1,
                     const float* __restrict__ xmax, const float* __restrict__ xavg,
                     float* __restrict__ r1)
{
    int idx = blockIdx.x * blockDim.x + threadIdx.x;
    if (idx >= BB * 512) return;
    int b = idx / 512, o = idx % 512;
    const float* w = ws1 + (size_t)o * 3072;
    float s = bs1[o];
    #pragma unroll 4
    for (int c = 0; c < 1024; c++)
        s += w[1024 + c] * xmax[b * 1024 + c] + w[2048 + c] * xavg[b * 1024 + c];
    r1[idx] = s;
}

// ---------------- ws3 (8x256) + log_softmax + transpose ----------------
__global__ void final_k(const float* __restrict__ s2, const float* __restrict__ ws3,
                        const float* __restrict__ bs3, float* __restrict__ out)
{
    __shared__ float w[8 * 256];
    __shared__ float bias[8];
    int t = threadIdx.x;
    for (int i = t; i < 2048; i += blockDim.x) w[i] = ws3[i];
    if (t < 8) bias[t] = bs3[t];
    __syncthreads();
    int idx = blockIdx.x * blockDim.x + t;
    int b = idx / NP, n = idx & (NP - 1);
    const float* sp = s2 + (size_t)b * 256 * NP + n;
    float l[8];
    #pragma unroll
    for (int k = 0; k < 8; k++) l[k] = bias[k];
    for (int c = 0; c < 256; c++) {
        float v = sp[(size_t)c * NP];
        #pragma unroll
        for (int k = 0; k < 8; k++) l[k] = fmaf(w[k * 256 + c], v, l[k]);
    }
    float m = l[0];
    #pragma unroll
    for (int k = 1; k < 8; k++) m = fmaxf(m, l[k]);
    float s = 0.f;
    #pragma unroll
    for (int k = 0; k < 8; k++) s += expf(l[k] - m);
    float lse = m + logf(s);
    #pragma unroll
    for (int k = 0; k < 8; k++)
        out[((size_t)b * NP + n) * 8 + k] = l[k] - lse;
}

// ---------------- host launch ----------------
extern "C" void kernel_launch(void* const* d_in, const int* in_sizes, int n_in,
                              void* d_out, int out_size)
{
    const float* x      = (const float*)d_in[0];
    const float* w1     = (const float*)d_in[1];
    const float* bn1_g  = (const float*)d_in[2];
    const float* bn1_b  = (const float*)d_in[3];
    const float* w2     = (const float*)d_in[4];
    const float* bn2_g  = (const float*)d_in[5];
    const float* bn2_b  = (const float*)d_in[6];
    const float* sa_wqk = (const float*)d_in[7];
    const float* sa_wv  = (const float*)d_in[8];
    const float* sa_bv  = (const float*)d_in[9];
    const float* sa_wt  = (const float*)d_in[10];
    const float* sa_bt  = (const float*)d_in[11];
    const float* sa_bng = (const float*)d_in[12];
    const float* sa_bnb = (const float*)d_in[13];
    const float* wf     = (const float*)d_in[14];
    const float* bnf_g  = (const float*)d_in[15];
    const float* bnf_b  = (const float*)d_in[16];
    const float* ws1    = (const float*)d_in[17];
    const float* bs1    = (const float*)d_in[18];
    const float* bns1_g = (const float*)d_in[19];
    const float* bns1_b = (const float*)d_in[20];
    const float* ws2    = (const float*)d_in[21];
    const float* bs2    = (const float*)d_in[22];
    const float* bns2_g = (const float*)d_in[23];
    const float* bns2_b = (const float*)d_in[24];
    const float* ws3    = (const float*)d_in[25];
    const float* bs3    = (const float*)d_in[26];
    float* out = (float*)d_out;

    float *c1, *h0, *q, *v, *u, *attn, *colsum, *feats, *hf, *xmax, *xavg, *r1, *s1, *s2;
    cudaGetSymbolAddress((void**)&c1,     g_c1);
    cudaGetSymbolAddress((void**)&h0,     g_h0);
    cudaGetSymbolAddress((void**)&q,      g_q);
    cudaGetSymbolAddress((void**)&v,      g_v);
    cudaGetSymbolAddress((void**)&u,      g_u);
    cudaGetSymbolAddress((void**)&attn,   g_attn);
    cudaGetSymbolAddress((void**)&colsum, g_colsum);
    cudaGetSymbolAddress((void**)&feats,  g_feats);
    cudaGetSymbolAddress((void**)&hf,     g_hf);
    cudaGetSymbolAddress((void**)&xmax,   g_xmax);
    cudaGetSymbolAddress((void**)&xavg,   g_xavg);
    cudaGetSymbolAddress((void**)&r1,     g_r1);
    cudaGetSymbolAddress((void**)&s1,     g_s1);
    cudaGetSymbolAddress((void**)&s2,     g_s2);

    const float INV = 0.999995000037499219f;   // 1/sqrt(1 + 1e-5)
    const size_t AT = (size_t)NP * NP;
    dim3 blk(256);

    // conv1: 3 -> 128, bn+relu
    conv1_k<<<(BB * 128 * NP) / 256, blk>>>(x, w1, bn1_g, bn1_b, INV, c1);

    // conv2: 128 -> 128, bn+relu
    gemm_k<false,1,0,false><<<dim3(NP/64, 2, BB), blk>>>(128, NP, 128, 128,
        w2, 0, c1, (size_t)128*NP, h0, (size_t)128*NP,
        nullptr, 0, bn2_g, bn2_b, INV, nullptr, 0, nullptr, 0, 0.f);

    for (int i = 0; i < 4; i++) {
        const float* hin = (i == 0) ? h0 : feats + (size_t)(i - 1) * 128 * NP;
        size_t sHin = (i == 0) ? (size_t)128 * NP : (size_t)512 * NP;

        // q = wqk @ h  (32 x 4096) fp32
        gemm_k<false,0,0,false><<<dim3(NP/64, 1, BB), blk>>>(32, NP, 128, 128,
            sa_wqk + (size_t)i*32*128, 0, hin, sHin, q, (size_t)32*NP,
            nullptr, 0, nullptr, nullptr, 1.f, nullptr, 0, nullptr, 0, 0.f);

        // energy = q^T q  (4096 x 4096) fp32
        gemm_k<true,0,0,false><<<dim3(NP/64, NP/64, BB), blk>>>(NP, NP, 32, NP,
            q, (size_t)32*NP, q, (size_t)32*NP, attn, AT,
            nullptr, 0, nullptr, nullptr, 1.f, nullptr, 0, nullptr, 0, 0.f);

        softmax_rows<<<BB * NP, blk>>>(attn);
        colsum_k<<<(BB * NP) / 256, blk>>>(attn, colsum);

        // v = wv @ h + bv  fp32
        gemm_k<false,0,0,false><<<dim3(NP/64, 2, BB), blk>>>(128, NP, 128, 128,
            sa_wv + (size_t)i*128*128, 0, hin, sHin, v, (size_t)128*NP,
            sa_bv + (size_t)i*128, 0, nullptr, nullptr, 1.f, nullptr, 0, nullptr, 0, 0.f);

        // u = h - (v @ attn) / (1e-9 + colsum)   [tf32 tensor]
        tgemm_k<64,0,2,true><<<dim3(NP/64, 1, BB), blk>>>(128, NP, NP, NP,
            v, (size_t)128*NP, attn, AT, u, (size_t)128*NP,
            nullptr, 0, nullptr, nullptr, 1.f, hin, sHin, colsum, (size_t)NP, 0.f);

        // h_new = h + relu(bn(wt @ u + bt))  -> feats block i  (fp32)
        gemm_k<false,1,1,false><<<dim3(NP/64, 2, BB), blk>>>(128, NP, 128, 128,
            sa_wt + (size_t)i*128*128, 0, u, (size_t)128*NP,
            feats + (size_t)i*128*NP, (size_t)512*NP,
            sa_bt + (size_t)i*128, 0, sa_bng + (size_t)i*128, sa_bnb + (size_t)i*128, INV,
            hin, sHin, nullptr, 0, 0.f);
    }

    // wf: 512 -> 1024, bn + leaky_relu(0.2)  [tf32 tensor]
    tgemm_k<128,2,0,false><<<dim3(NP/128, 1024/128, BB), blk>>>(1024, NP, 512, 512,
        wf, 0, feats, (size_t)512*NP, hf, (size_t)1024*NP,
        nullptr, 0, bnf_g, bnf_b, INV, nullptr, 0, nullptr, 0, 0.2f);

    pool_k<<<BB * 1024, blk>>>(hf, xmax, xavg);
    r1_k<<<(BB * 512 + 255) / 256, blk>>>(ws1, bs1, xmax, xavg, r1);

    // ws1 (first 1024 input channels of 3072; pooled part folded into r1)  [tf32]
    tgemm_k<128,1,0,false><<<dim3(NP/128, 512/128, BB), blk>>>(512, NP, 1024, 3072,
        ws1, 0, hf, (size_t)1024*NP, s1, (size_t)512*NP,
        r1, 512, bns1_g, bns1_b, INV, nullptr, 0, nullptr, 0, 0.f);

    // ws2: 512 -> 256, bn + relu  [tf32]
    tgemm_k<128,1,0,false><<<dim3(NP/128, 256/128, BB), blk>>>(256, NP, 512, 512,
        ws2, 0, s1, (size_t)512*NP, s2, (size_t)256*NP,
        bs2, 0, bns2_g, bns2_b, INV, nullptr, 0, nullptr, 0, 0.f);

    // ws3 + log_softmax + transpose
    final_k<<<(BB * NP) / 256, blk>>>(s2, ws3, bs3, out);
}

// round 5
// speedup vs baseline: 2.4803x; 1.9634x over previous
#include <cuda_runtime.h>
#include <cstdint>

#define NP 4096
#define BB 2

// ---------------- scratch (static device globals; no allocation) ----------------
__device__ float g_c1[BB*128*NP];
__device__ float g_h0[BB*128*NP];
__device__ float g_q [BB*32*NP];
__device__ float g_v [BB*128*NP];
__device__ float g_u [BB*128*NP];
__device__ float g_rowm[BB*NP];
__device__ float g_rowsinv[BB*NP];
__device__ float g_feats[BB*512*NP];
__device__ float g_hf[BB*1024*NP];
__device__ float g_xmax[BB*1024];
__device__ float g_xavg[BB*1024];
__device__ float g_r1[BB*512];
__device__ float g_s1[BB*512*NP];
__device__ float g_s2[BB*256*NP];

// ---------------- PTX helpers ----------------
__device__ __forceinline__ uint32_t smem_u32(const void* p) {
    return (uint32_t)__cvta_generic_to_shared(p);
}
__device__ __forceinline__ void cpa16(uint32_t s, const void* g) {
    asm volatile("cp.async.cg.shared.global [%0], [%1], 16;" :: "r"(s), "l"(g));
}
__device__ __forceinline__ void cpa_commit() { asm volatile("cp.async.commit_group;"); }
__device__ __forceinline__ void cpa_wait0()  { asm volatile("cp.async.wait_group 0;"); }
__device__ __forceinline__ uint32_t f2tf(float f) {
    uint32_t r;
    asm("cvt.rna.tf32.f32 %0, %1;" : "=r"(r) : "f"(f));
    return r;
}
__device__ __forceinline__ void split_tf(float x, uint32_t& hi, uint32_t& lo) {
    hi = f2tf(x);
    lo = f2tf(x - __uint_as_float(hi));
}
__device__ __forceinline__ void mma_tf32(float* c, const uint32_t* a, const uint32_t* b) {
    asm volatile(
        "mma.sync.aligned.m16n8k8.row.col.f32.tf32.tf32.f32 "
        "{%0,%1,%2,%3}, {%4,%5,%6,%7}, {%8,%9}, {%0,%1,%2,%3};"
        : "+f"(c[0]), "+f"(c[1]), "+f"(c[2]), "+f"(c[3])
        : "r"(a[0]), "r"(a[1]), "r"(a[2]), "r"(a[3]), "r"(b[0]), "r"(b[1]));
}

// =====================================================================
// PASS 1: flash row stats.  Block: 64 rows i; loop over j in 64-tiles.
// e[i,j] = sum_d q[d,i] q[d,j]  computed with tf32 hi/lo split (fp32-accurate)
// =====================================================================
__global__ __launch_bounds__(256) void attn_stats_k(
    const float* __restrict__ q, float* __restrict__ rowm, float* __restrict__ rowsinv)
{
    constexpr int QS = 72;
    __shared__ __align__(16) float qi_s[32 * QS];
    __shared__ __align__(16) float qj_s[2][32 * QS];
    __shared__ float red_m[64 * 16], red_s[64 * 16];

    const int b = blockIdx.y;
    const int i0 = blockIdx.x * 64;
    const float* qb = q + (size_t)b * 32 * NP;
    const int tid = threadIdx.x;
    const int wid = tid >> 5, lane = tid & 31;
    const int lr = lane >> 2, lc = lane & 3;
    const int wi = wid >> 2;      // 0..1 (32 i each)
    const int wj = wid & 3;       // 0..3 (16 j each)

    // qi: 32 rows x 64 cols (cols i0..i0+63) -> 512 float4
    for (int t = tid; t < 512; t += 256) {
        int r = t >> 4, s4 = (t & 15) * 4;
        *(float4*)&qi_s[r * QS + s4] = *(const float4*)&qb[(size_t)r * NP + i0 + s4];
    }
    // preload qj tile 0
    for (int t = tid; t < 512; t += 256) {
        int r = t >> 4, s4 = (t & 15) * 4;
        cpa16(smem_u32(&qj_s[0][r * QS + s4]), qb + (size_t)r * NP + s4);
    }
    cpa_commit();

    float m_t[4], s_t[4];
    #pragma unroll
    for (int k = 0; k < 4; k++) { m_t[k] = -1e30f; s_t[k] = 0.f; }

    for (int jt = 0; jt < 64; jt++) {
        cpa_wait0(); __syncthreads();
        int buf = jt & 1;
        if (jt + 1 < 64) {
            int j0n = (jt + 1) * 64;
            for (int t = tid; t < 512; t += 256) {
                int r = t >> 4, s4 = (t & 15) * 4;
                cpa16(smem_u32(&qj_s[buf ^ 1][r * QS + s4]), qb + (size_t)r * NP + j0n + s4);
            }
            cpa_commit();
        }
        float acc[2][2][4];
        #pragma unroll
        for (int a = 0; a < 2; a++)
            #pragma unroll
            for (int c = 0; c < 2; c++)
                #pragma unroll
                for (int e = 0; e < 4; e++) acc[a][c][e] = 0.f;

        #pragma unroll
        for (int ks = 0; ks < 4; ks++) {
            int k = ks * 8 + lc;
            uint32_t ah[2][4], al[2][4];
            #pragma unroll
            for (int mt = 0; mt < 2; mt++) {
                int ib = wi * 32 + mt * 16 + lr;
                split_tf(qi_s[k * QS + ib],           ah[mt][0], al[mt][0]);
                split_tf(qi_s[k * QS + ib + 8],       ah[mt][1], al[mt][1]);
                split_tf(qi_s[(k + 4) * QS + ib],     ah[mt][2], al[mt][2]);
                split_tf(qi_s[(k + 4) * QS + ib + 8], ah[mt][3], al[mt][3]);
            }
            uint32_t bh[2][2], bl[2][2];
            #pragma unroll
            for (int nt = 0; nt < 2; nt++) {
                int jb = wj * 16 + nt * 8 + lr;
                split_tf(qj_s[buf][k * QS + jb],       bh[nt][0], bl[nt][0]);
                split_tf(qj_s[buf][(k + 4) * QS + jb], bh[nt][1], bl[nt][1]);
            }
            #pragma unroll
            for (int mt = 0; mt < 2; mt++)
                #pragma unroll
                for (int nt = 0; nt < 2; nt++) {
                    mma_tf32(acc[mt][nt], ah[mt], bh[nt]);
                    mma_tf32(acc[mt][nt], ah[mt], bl[nt]);
                    mma_tf32(acc[mt][nt], al[mt], bh[nt]);
                }
        }
        // online row-stat update
        #pragma unroll
        for (int mt = 0; mt < 2; mt++) {
            #pragma unroll
            for (int half = 0; half < 2; half++) {
                int idx = mt * 2 + half;
                float v0 = acc[mt][0][half * 2], v1 = acc[mt][0][half * 2 + 1];
                float v2 = acc[mt][1][half * 2], v3 = acc[mt][1][half * 2 + 1];
                float tmax = fmaxf(fmaxf(v0, v1), fmaxf(v2, v3));
                float mnew = fmaxf(m_t[idx], tmax);
                float sc = __expf(m_t[idx] - mnew);
                float add = __expf(v0 - mnew) + __expf(v1 - mnew)
                          + __expf(v2 - mnew) + __expf(v3 - mnew);
                s_t[idx] = s_t[idx] * sc + add;
                m_t[idx] = mnew;
            }
        }
    }
    // cross-thread reduction (16 threads share a row)
    #pragma unroll
    for (int mt = 0; mt < 2; mt++)
        #pragma unroll
        for (int half = 0; half < 2; half++) {
            int row = wi * 32 + mt * 16 + half * 8 + lr;
            int slot = wj * 4 + lc;
            red_m[row * 16 + slot] = m_t[mt * 2 + half];
            red_s[row * 16 + slot] = s_t[mt * 2 + half];
        }
    __syncthreads();
    if (tid < 64) {
        float mt_ = -1e30f;
        #pragma unroll
        for (int k = 0; k < 16; k++) mt_ = fmaxf(mt_, red_m[tid * 16 + k]);
        float s = 0.f;
        #pragma unroll
        for (int k = 0; k < 16; k++)
            s += red_s[tid * 16 + k] * __expf(red_m[tid * 16 + k] - mt_);
        rowm[(size_t)b * NP + i0 + tid] = mt_;
        rowsinv[(size_t)b * NP + i0 + tid] = 1.f / s;
    }
}

// =====================================================================
// PASS 2: fused energy->softmax->colsum->v@attn->residual.
// Block: 64 output columns j, all 128 channels c. Loop over i in 64-tiles.
// =====================================================================
#define FUSE_SMEM_FLOATS 31040   // qj 2304 | qi 2*2304 | v 2*9728 | attn 4608 | cs 64
__global__ __launch_bounds__(256) void attn_fuse_k(
    const float* __restrict__ q, const float* __restrict__ v,
    const float* __restrict__ rowm, const float* __restrict__ rowsinv,
    const float* __restrict__ hin, size_t sHin,
    float* __restrict__ u)
{
    extern __shared__ __align__(16) float sm[];
    float* qj_s = sm;                 // [32][72]
    float* qi_s = sm + 2304;          // [2][32*72]
    float* v_s  = sm + 6912;          // [2][128*76]
    float* at_s = sm + 26368;         // [64][72]
    float* cs_s = sm + 30976;         // [64]

    const int b = blockIdx.y;
    const int n0 = blockIdx.x * 64;
    const float* qb = q + (size_t)b * 32 * NP;
    const float* vb = v + (size_t)b * 128 * NP;
    const int tid = threadIdx.x;
    const int wid = tid >> 5, lane = tid & 31;
    const int lr = lane >> 2, lc = lane & 3;
    const int w1 = wid >> 1;      // 0..3
    const int w2 = wid & 1;       // 0..1

    if (tid < 64) cs_s[tid] = 0.f;

    // prologue: qj + tile 0 of qi, v
    for (int t = tid; t < 512; t += 256) {
        int r = t >> 4, s4 = (t & 15) * 4;
        cpa16(smem_u32(qj_s + r * 72 + s4), qb + (size_t)r * NP + n0 + s4);
    }
    for (int t = tid; t < 512; t += 256) {
        int r = t >> 4, s4 = (t & 15) * 4;
        cpa16(smem_u32(qi_s + r * 72 + s4), qb + (size_t)r * NP + s4);
    }
    for (int t = tid; t < 2048; t += 256) {
        int r = t >> 4, s4 = (t & 15) * 4;
        cpa16(smem_u32(v_s + r * 76 + s4), vb + (size_t)r * NP + s4);
    }
    cpa_commit();

    float acc_v[2][4][4];
    #pragma unroll
    for (int a = 0; a < 2; a++)
        #pragma unroll
        for (int c = 0; c < 4; c++)
            #pragma unroll
            for (int e = 0; e < 4; e++) acc_v[a][c][e] = 0.f;
    float cs_part[8];
    #pragma unroll
    for (int p = 0; p < 8; p++) cs_part[p] = 0.f;

    for (int it = 0; it < 64; it++) {
        cpa_wait0(); __syncthreads();
        int buf = it & 1;
        if (it + 1 < 64) {
            int i0n = (it + 1) * 64;
            float* qin = qi_s + (buf ^ 1) * 2304;
            float* vn  = v_s + (buf ^ 1) * 9728;
            for (int t = tid; t < 512; t += 256) {
                int r = t >> 4, s4 = (t & 15) * 4;
                cpa16(smem_u32(qin + r * 72 + s4), qb + (size_t)r * NP + i0n + s4);
            }
            for (int t = tid; t < 2048; t += 256) {
                int r = t >> 4, s4 = (t & 15) * 4;
                cpa16(smem_u32(vn + r * 76 + s4), vb + (size_t)r * NP + i0n + s4);
            }
            cpa_commit();
        }
        const int i0 = it * 64;
        const float* qip = qi_s + buf * 2304;
        const float* vp  = v_s + buf * 9728;

        // ---- phase e: 64i x 64j; warp tile 16i x 32j (wi=w1, wj=w2) ----
        float ae[4][4];
        #pragma unroll
        for (int c = 0; c < 4; c++)
            #pragma unroll
            for (int e = 0; e < 4; e++) ae[c][e] = 0.f;
        #pragma unroll
        for (int ks = 0; ks < 4; ks++) {
            int k = ks * 8 + lc;
            int ib = w1 * 16 + lr;
            uint32_t ah[4], al[4];
            split_tf(qip[k * 72 + ib],           ah[0], al[0]);
            split_tf(qip[k * 72 + ib + 8],       ah[1], al[1]);
            split_tf(qip[(k + 4) * 72 + ib],     ah[2], al[2]);
            split_tf(qip[(k + 4) * 72 + ib + 8], ah[3], al[3]);
            #pragma unroll
            for (int nt = 0; nt < 4; nt++) {
                int jb = w2 * 32 + nt * 8 + lr;
                uint32_t bh[2], bl[2];
                split_tf(qj_s[k * 72 + jb],       bh[0], bl[0]);
                split_tf(qj_s[(k + 4) * 72 + jb], bh[1], bl[1]);
                mma_tf32(ae[nt], ah, bh);
                mma_tf32(ae[nt], ah, bl);
                mma_tf32(ae[nt], al, bh);
            }
        }
        // exp + store attn tile + colsum partials
        {
            int gi = b * NP + i0 + w1 * 16 + lr;
            float m0 = rowm[gi],     m1 = rowm[gi + 8];
            float si0 = rowsinv[gi], si1 = rowsinv[gi + 8];
            #pragma unroll
            for (int nt = 0; nt < 4; nt++) {
                float e00 = __expf(ae[nt][0] - m0) * si0;
                float e01 = __expf(ae[nt][1] - m0) * si0;
                float e10 = __expf(ae[nt][2] - m1) * si1;
                float e11 = __expf(ae[nt][3] - m1) * si1;
                int jb = w2 * 32 + nt * 8 + lc * 2;
                int ib = w1 * 16 + lr;
                *(float2*)&at_s[ib * 72 + jb]       = make_float2(e00, e01);
                *(float2*)&at_s[(ib + 8) * 72 + jb] = make_float2(e10, e11);
                cs_part[nt * 2]     += e00 + e10;
                cs_part[nt * 2 + 1] += e01 + e11;
            }
        }
        __syncthreads();

        // ---- phase v: 128c x 64j, K=64; warp tile 32c x 32j (wm=w1, wn=w2) ----
        #pragma unroll
        for (int ks = 0; ks < 8; ks++) {
            int k = ks * 8 + lc;
            uint32_t av[2][4];
            #pragma unroll
            for (int mt = 0; mt < 2; mt++) {
                int cb = w1 * 32 + mt * 16 + lr;
                av[mt][0] = f2tf(vp[cb * 76 + k]);
                av[mt][1] = f2tf(vp[(cb + 8) * 76 + k]);
                av[mt][2] = f2tf(vp[cb * 76 + k + 4]);
                av[mt][3] = f2tf(vp[(cb + 8) * 76 + k + 4]);
            }
            #pragma unroll
            for (int nt = 0; nt < 4; nt++) {
                int jb = w2 * 32 + nt * 8 + lr;
                uint32_t bv[2];
                bv[0] = f2tf(at_s[k * 72 + jb]);
                bv[1] = f2tf(at_s[(k + 4) * 72 + jb]);
                #pragma unroll
                for (int mt = 0; mt < 2; mt++)
                    mma_tf32(acc_v[mt][nt], av[mt], bv);
            }
        }
    }

    // colsum reduce + invert
    #pragma unroll
    for (int p = 0; p < 8; p++) {
        int jb = w2 * 32 + (p >> 1) * 8 + lc * 2 + (p & 1);
        atomicAdd(&cs_s[jb], cs_part[p]);
    }
    __syncthreads();
    if (tid < 64) cs_s[tid] = 1.f / (1e-9f + cs_s[tid]);
    __syncthreads();

    // epilogue: u = h - x_r * csinv
    #pragma unroll
    for (int mt = 0; mt < 2; mt++) {
        #pragma unroll
        for (int half = 0; half < 2; half++) {
            int c = w1 * 32 + mt * 16 + half * 8 + lr;
            #pragma unroll
            for (int nt = 0; nt < 4; nt++) {
                int jb = w2 * 32 + nt * 8 + lc * 2;
                float ci0 = cs_s[jb], ci1 = cs_s[jb + 1];
                float2 hv = *(const float2*)&hin[(size_t)b * sHin + (size_t)c * NP + n0 + jb];
                float2 o;
                o.x = hv.x - acc_v[mt][nt][half * 2]     * ci0;
                o.y = hv.y - acc_v[mt][nt][half * 2 + 1] * ci1;
                *(float2*)&u[(size_t)b * 128 * NP + (size_t)c * NP + n0 + jb] = o;
            }
        }
    }
}

// ---------------- tf32 tensor-core GEMM with fused epilogues ----------------
template<int BN>
__device__ __forceinline__ void t_load(float* As, float* Bs,
    const float* __restrict__ Ab, const float* __restrict__ Bb,
    int tid, int kt, int lda, int N)
{
    constexpr int ASTR = 20;
    constexpr int BSTR = BN + 8;
    #pragma unroll
    for (int i = 0; i < 2; i++) {
        int idx = tid + i * 256;
        int row = idx >> 2, seg = (idx & 3) * 4;
        cpa16(smem_u32(As + row * ASTR + seg), Ab + (size_t)row * lda + kt * 16 + seg);
    }
    constexpr int BF4 = BN / 64;
    #pragma unroll
    for (int i = 0; i < BF4; i++) {
        int idx = tid + i * 256;
        int row = idx / (BN / 4), seg = (idx % (BN / 4)) * 4;
        cpa16(smem_u32(Bs + row * BSTR + seg), Bb + (size_t)(kt * 16 + row) * N + seg);
    }
}

template<int BN, int ACT, int RES, bool COLDIV>
__global__ __launch_bounds__(256) void tgemm_k(int M, int N, int K, int lda,
    const float* __restrict__ A, size_t sA,
    const float* __restrict__ B, size_t sB,
    float* __restrict__ C, size_t sC,
    const float* __restrict__ rb, size_t sRB,
    const float* __restrict__ bng, const float* __restrict__ bnb, float bninv,
    const float* __restrict__ res, size_t sRes,
    const float* __restrict__ cs, size_t sCS,
    float slope)
{
    constexpr int BM = 128, BK = 16;
    constexpr int ASTR = 20;
    constexpr int BSTR = BN + 8;
    constexpr int WN = BN / 4;
    constexpr int NT = WN / 8;
    __shared__ __align__(16) float As[2][BM * ASTR];
    __shared__ __align__(16) float Bs[2][BK * BSTR];

    const int b = blockIdx.z;
    const int m0 = blockIdx.y * BM, n0 = blockIdx.x * BN;
    const float* Ab = A + (size_t)b * sA + (size_t)m0 * lda;
    const float* Bb = B + (size_t)b * sB + n0;
    const int tid = threadIdx.x;
    const int wid = tid >> 5, lane = tid & 31;
    const int wm = wid >> 2, wn = wid & 3;
    const int lr = lane >> 2, lc = lane & 3;

    float acc[4][NT][4];
    #pragma unroll
    for (int i = 0; i < 4; i++)
        #pragma unroll
        for (int j = 0; j < NT; j++)
            #pragma unroll
            for (int e = 0; e < 4; e++) acc[i][j][e] = 0.f;

    const int nk = K / BK;
    t_load<BN>(As[0], Bs[0], Ab, Bb, tid, 0, lda, N);
    cpa_commit();

    for (int kt = 0; kt < nk; kt++) {
        cpa_wait0();
        __syncthreads();
        int buf = kt & 1;
        if (kt + 1 < nk) {
            t_load<BN>(As[buf ^ 1], Bs[buf ^ 1], Ab, Bb, tid, kt + 1, lda, N);
            cpa_commit();
        }
        #pragma unroll
        for (int ks = 0; ks < 2; ks++) {
            const float* Ap = &As[buf][0];
            const float* Bp = &Bs[buf][0];
            uint32_t af[4][4];
            #pragma unroll
            for (int mt = 0; mt < 4; mt++) {
                int r = wm * 64 + mt * 16 + lr;
                int c = ks * 8 + lc;
                af[mt][0] = f2tf(Ap[(r    ) * ASTR + c    ]);
                af[mt][1] = f2tf(Ap[(r + 8) * ASTR + c    ]);
                af[mt][2] = f2tf(Ap[(r    ) * ASTR + c + 4]);
                af[mt][3] = f2tf(Ap[(r + 8) * ASTR + c + 4]);
            }
            uint32_t bf[NT][2];
            #pragma unroll
            for (int nt = 0; nt < NT; nt++) {
                int cgl = wn * WN + nt * 8 + lr;
                int k = ks * 8 + lc;
                bf[nt][0] = f2tf(Bp[(k    ) * BSTR + cgl]);
                bf[nt][1] = f2tf(Bp[(k + 4) * BSTR + cgl]);
            }
            #pragma unroll
            for (int mt = 0; mt < 4; mt++)
                #pragma unroll
                for (int nt = 0; nt < NT; nt++)
                    mma_tf32(acc[mt][nt], af[mt], bf[nt]);
        }
        __syncthreads();
    }

    #pragma unroll
    for (int mt = 0; mt < 4; mt++) {
        #pragma unroll
        for (int h = 0; h < 2; h++) {
            int mm = m0 + wm * 64 + mt * 16 + h * 8 + lr;
            float scale = (bng ? bng[mm] : 1.f) * bninv;
            float shift = bnb ? bnb[mm] : 0.f;
            float rbv   = rb  ? rb[(size_t)b * sRB + mm] : 0.f;
            #pragma unroll
            for (int nt = 0; nt < NT; nt++) {
                int n = n0 + wn * WN + nt * 8 + lc * 2;
                float v0 = acc[mt][nt][h * 2 + 0];
                float v1 = acc[mt][nt][h * 2 + 1];
                if (COLDIV) {
                    v0 = v0 / (1e-9f + cs[(size_t)b * sCS + n]);
                    v1 = v1 / (1e-9f + cs[(size_t)b * sCS + n + 1]);
                }
                v0 = (v0 + rbv) * scale + shift;
                v1 = (v1 + rbv) * scale + shift;
                if (ACT == 1) { v0 = fmaxf(v0, 0.f); v1 = fmaxf(v1, 0.f); }
                else if (ACT == 2) { v0 = v0 > 0.f ? v0 : slope * v0; v1 = v1 > 0.f ? v1 : slope * v1; }
                if (RES == 1) {
                    v0 = res[(size_t)b * sRes + (size_t)mm * N + n] + v0;
                    v1 = res[(size_t)b * sRes + (size_t)mm * N + n + 1] + v1;
                } else if (RES == 2) {
                    v0 = res[(size_t)b * sRes + (size_t)mm * N + n] - v0;
                    v1 = res[(size_t)b * sRes + (size_t)mm * N + n + 1] - v1;
                }
                *(float2*)&C[(size_t)b * sC + (size_t)mm * N + n] = make_float2(v0, v1);
            }
        }
    }
}

// ---------------- fp32 tiled SGEMM with fused epilogues (small GEMMs) ----------------
template<bool TA, int ACT, int RES, bool COLDIV>
__global__ void gemm_k(int M, int N, int K, int lda,
    const float* __restrict__ A, size_t sA,
    const float* __restrict__ B, size_t sB,
    float* __restrict__ C, size_t sC,
    const float* __restrict__ rb, size_t sRB,
    const float* __restrict__ bng, const float* __restrict__ bnb, float bninv,
    const float* __restrict__ res, size_t sRes,
    const float* __restrict__ cs, size_t sCS,
    float slope)
{
    __shared__ float As[16][68];
    __shared__ float Bs[16][68];
    const int b  = blockIdx.z;
    const float* Ab = A + (size_t)b * sA;
    const float* Bb = B + (size_t)b * sB;
    const int m0 = blockIdx.y * 64;
    const int n0 = blockIdx.x * 64;
    const int tid = threadIdx.x;
    const int tx = tid & 15, ty = tid >> 4;

    float acc[4][4];
    #pragma unroll
    for (int i = 0; i < 4; i++)
        #pragma unroll
        for (int j = 0; j < 4; j++) acc[i][j] = 0.f;

    for (int k0 = 0; k0 < K; k0 += 16) {
        if (TA) {
            int kk = tid >> 4, mq = tid & 15;
            float4 av = *(const float4*)&Ab[(size_t)(k0 + kk) * lda + m0 + mq * 4];
            *(float4*)&As[kk][mq * 4] = av;
        } else {
            int m = tid >> 2, kq = tid & 3;
            float4 av = make_float4(0.f, 0.f, 0.f, 0.f);
            if (m0 + m < M)
                av = *(const float4*)&Ab[(size_t)(m0 + m) * lda + k0 + kq * 4];
            As[kq * 4 + 0][m] = av.x;
            As[kq * 4 + 1][m] = av.y;
            As[kq * 4 + 2][m] = av.z;
            As[kq * 4 + 3][m] = av.w;
        }
        {
            int kk = tid >> 4, nq = tid & 15;
            float4 bv = *(const float4*)&Bb[(size_t)(k0 + kk) * N + n0 + nq * 4];
            *(float4*)&Bs[kk][nq * 4] = bv;
        }
        __syncthreads();
        #pragma unroll
        for (int k = 0; k < 16; k++) {
            float4 a4 = *(float4*)&As[k][ty * 4];
            float4 b4 = *(float4*)&Bs[k][tx * 4];
            float ar[4] = {a4.x, a4.y, a4.z, a4.w};
            float br[4] = {b4.x, b4.y, b4.z, b4.w};
            #pragma unroll
            for (int i = 0; i < 4; i++)
                #pragma unroll
                for (int j = 0; j < 4; j++)
                    acc[i][j] = fmaf(ar[i], br[j], acc[i][j]);
        }
        __syncthreads();
    }

    #pragma unroll
    for (int i = 0; i < 4; i++) {
        int m = m0 + ty * 4 + i;
        if (m >= M) continue;
        float scale = (bng ? bng[m] : 1.f) * bninv;
        float shift = bnb ? bnb[m] : 0.f;
        float rbv   = rb  ? rb[(size_t)b * sRB + m] : 0.f;
        #pragma unroll
        for (int j = 0; j < 4; j++) {
            int n = n0 + tx * 4 + j;
            float v = acc[i][j];
            if (COLDIV) v = v / (1e-9f + cs[(size_t)b * sCS + n]);
            v = (v + rbv) * scale + shift;
            if (ACT == 1) v = fmaxf(v, 0.f);
            else if (ACT == 2) v = v > 0.f ? v : slope * v;
            if (RES == 1)      v = res[(size_t)b * sRes + (size_t)m * N + n] + v;
            else if (RES == 2) v = res[(size_t)b * sRes + (size_t)m * N + n] - v;
            C[(size_t)b * sC + (size_t)m * N + n] = v;
        }
    }
}

// ---------------- conv1 ----------------
__global__ void conv1_k(const float* __restrict__ x, const float* __restrict__ w1,
                        const float* __restrict__ g, const float* __restrict__ bb,
                        float inv, float* __restrict__ out)
{
    int idx = blockIdx.x * blockDim.x + threadIdx.x;
    int n = idx & (NP - 1);
    int o = (idx / NP) & 127;
    int b = idx / (128 * NP);
    const float* xp = x + ((size_t)b * 15 + 9) * NP + n;
    float s = w1[o * 3 + 0] * xp[0] + w1[o * 3 + 1] * xp[NP] + w1[o * 3 + 2] * xp[2 * NP];
    s = s * g[o] * inv + bb[o];
    out[idx] = fmaxf(s, 0.f);
}

// ---------------- global max/mean pooling over N ----------------
__global__ void pool_k(const float* __restrict__ hf, float* __restrict__ xmax, float* __restrict__ xavg)
{
    int bc = blockIdx.x;
    const float* p = hf + (size_t)bc * NP;
    int t = threadIdx.x;
    float mx = -1e30f, sm = 0.f;
    for (int i = t; i < NP; i += 256) { float v = p[i]; mx = fmaxf(mx, v); sm += v; }
    __shared__ float rm[256], rs[256];
    rm[t] = mx; rs[t] = sm; __syncthreads();
    for (int s = 128; s > 0; s >>= 1) {
        if (t < s) { rm[t] = fmaxf(rm[t], rm[t + s]); rs[t] += rs[t + s]; }
        __syncthreads();
    }
    if (t == 0) { xmax[bc] = rm[0]; xavg[bc] = rs[0] * (1.f / NP); }
}

// ---------------- fold pooled channels of ws1 into per-row bias ----------------
__global__ void r1_k(const float* __restrict__ ws1, const float* __restrict__ bs1,
                     const float* __restrict__ xmax, const float* __restrict__ xavg,
                     float* __restrict__ r1)
{
    int idx = blockIdx.x * blockDim.x + threadIdx.x;
    if (idx >= BB * 512) return;
    int b = idx / 512, o = idx % 512;
    const float* w = ws1 + (size_t)o * 3072;
    float s = bs1[o];
    #pragma unroll 4
    for (int c = 0; c < 1024; c++)
        s += w[1024 + c] * xmax[b * 1024 + c] + w[2048 + c] * xavg[b * 1024 + c];
    r1[idx] = s;
}

// ---------------- ws3 (8x256) + log_softmax + transpose ----------------
__global__ void final_k(const float* __restrict__ s2, const float* __restrict__ ws3,
                        const float* __restrict__ bs3, float* __restrict__ out)
{
    __shared__ float w[8 * 256];
    __shared__ float bias[8];
    int t = threadIdx.x;
    for (int i = t; i < 2048; i += blockDim.x) w[i] = ws3[i];
    if (t < 8) bias[t] = bs3[t];
    __syncthreads();
    int idx = blockIdx.x * blockDim.x + t;
    int b = idx / NP, n = idx & (NP - 1);
    const float* sp = s2 + (size_t)b * 256 * NP + n;
    float l[8];
    #pragma unroll
    for (int k = 0; k < 8; k++) l[k] = bias[k];
    for (int c = 0; c < 256; c++) {
        float v = sp[(size_t)c * NP];
        #pragma unroll
        for (int k = 0; k < 8; k++) l[k] = fmaf(w[k * 256 + c], v, l[k]);
    }
    float m = l[0];
    #pragma unroll
    for (int k = 1; k < 8; k++) m = fmaxf(m, l[k]);
    float s = 0.f;
    #pragma unroll
    for (int k = 0; k < 8; k++) s += expf(l[k] - m);
    float lse = m + logf(s);
    #pragma unroll
    for (int k = 0; k < 8; k++)
        out[((size_t)b * NP + n) * 8 + k] = l[k] - lse;
}

// ---------------- host launch ----------------
extern "C" void kernel_launch(void* const* d_in, const int* in_sizes, int n_in,
                              void* d_out, int out_size)
{
    const float* x      = (const float*)d_in[0];
    const float* w1     = (const float*)d_in[1];
    const float* bn1_g  = (const float*)d_in[2];
    const float* bn1_b  = (const float*)d_in[3];
    const float* w2     = (const float*)d_in[4];
    const float* bn2_g  = (const float*)d_in[5];
    const float* bn2_b  = (const float*)d_in[6];
    const float* sa_wqk = (const float*)d_in[7];
    const float* sa_wv  = (const float*)d_in[8];
    const float* sa_bv  = (const float*)d_in[9];
    const float* sa_wt  = (const float*)d_in[10];
    const float* sa_bt  = (const float*)d_in[11];
    const float* sa_bng = (const float*)d_in[12];
    const float* sa_bnb = (const float*)d_in[13];
    const float* wf     = (const float*)d_in[14];
    const float* bnf_g  = (const float*)d_in[15];
    const float* bnf_b  = (const float*)d_in[16];
    const float* ws1    = (const float*)d_in[17];
    const float* bs1    = (const float*)d_in[18];
    const float* bns1_g = (const float*)d_in[19];
    const float* bns1_b = (const float*)d_in[20];
    const float* ws2    = (const float*)d_in[21];
    const float* bs2    = (const float*)d_in[22];
    const float* bns2_g = (const float*)d_in[23];
    const float* bns2_b = (const float*)d_in[24];
    const float* ws3    = (const float*)d_in[25];
    const float* bs3    = (const float*)d_in[26];
    float* out = (float*)d_out;

    float *c1, *h0, *q, *v, *u, *rowm, *rowsinv, *feats, *hf, *xmax, *xavg, *r1, *s1, *s2;
    cudaGetSymbolAddress((void**)&c1,      g_c1);
    cudaGetSymbolAddress((void**)&h0,      g_h0);
    cudaGetSymbolAddress((void**)&q,       g_q);
    cudaGetSymbolAddress((void**)&v,       g_v);
    cudaGetSymbolAddress((void**)&u,       g_u);
    cudaGetSymbolAddress((void**)&rowm,    g_rowm);
    cudaGetSymbolAddress((void**)&rowsinv, g_rowsinv);
    cudaGetSymbolAddress((void**)&feats,   g_feats);
    cudaGetSymbolAddress((void**)&hf,      g_hf);
    cudaGetSymbolAddress((void**)&xmax,    g_xmax);
    cudaGetSymbolAddress((void**)&xavg,    g_xavg);
    cudaGetSymbolAddress((void**)&r1,      g_r1);
    cudaGetSymbolAddress((void**)&s1,      g_s1);
    cudaGetSymbolAddress((void**)&s2,      g_s2);

    const float INV = 0.999995000037499219f;   // 1/sqrt(1 + 1e-5)
    dim3 blk(256);
    const int FUSE_SMEM = FUSE_SMEM_FLOATS * 4;
    cudaFuncSetAttribute(attn_fuse_k, cudaFuncAttributeMaxDynamicSharedMemorySize, FUSE_SMEM);

    // conv1: 3 -> 128, bn+relu
    conv1_k<<<(BB * 128 * NP) / 256, blk>>>(x, w1, bn1_g, bn1_b, INV, c1);

    // conv2: 128 -> 128, bn+relu
    gemm_k<false,1,0,false><<<dim3(NP/64, 2, BB), blk>>>(128, NP, 128, 128,
        w2, 0, c1, (size_t)128*NP, h0, (size_t)128*NP,
        nullptr, 0, bn2_g, bn2_b, INV, nullptr, 0, nullptr, 0, 0.f);

    for (int i = 0; i < 4; i++) {
        const float* hin = (i == 0) ? h0 : feats + (size_t)(i - 1) * 128 * NP;
        size_t sHin = (i == 0) ? (size_t)128 * NP : (size_t)512 * NP;

        // q = wqk @ h  (32 x 4096) fp32
        gemm_k<false,0,0,false><<<dim3(NP/64, 1, BB), blk>>>(32, NP, 128, 128,
            sa_wqk + (size_t)i*32*128, 0, hin, sHin, q, (size_t)32*NP,
            nullptr, 0, nullptr, nullptr, 1.f, nullptr, 0, nullptr, 0, 0.f);

        // pass 1: row softmax stats
        attn_stats_k<<<dim3(NP/64, BB), blk>>>(q, rowm, rowsinv);

        // v = wv @ h + bv  fp32
        gemm_k<false,0,0,false><<<dim3(NP/64, 2, BB), blk>>>(128, NP, 128, 128,
            sa_wv + (size_t)i*128*128, 0, hin, sHin, v, (size_t)128*NP,
            sa_bv + (size_t)i*128, 0, nullptr, nullptr, 1.f, nullptr, 0, nullptr, 0, 0.f);

        // pass 2: fused energy->softmax->colsum->v@attn->residual: u = h - x_r
        attn_fuse_k<<<dim3(NP/64, BB), blk, FUSE_SMEM>>>(q, v, rowm, rowsinv, hin, sHin, u);

        // h_new = h + relu(bn(wt @ u + bt))  -> feats block i  (fp32)
        gemm_k<false,1,1,false><<<dim3(NP/64, 2, BB), blk>>>(128, NP, 128, 128,
            sa_wt + (size_t)i*128*128, 0, u, (size_t)128*NP,
            feats + (size_t)i*128*NP, (size_t)512*NP,
            sa_bt + (size_t)i*128, 0, sa_bng + (size_t)i*128, sa_bnb + (size_t)i*128, INV,
            hin, sHin, nullptr, 0, 0.f);
    }

    // wf: 512 -> 1024, bn + leaky_relu(0.2)  [tf32 tensor]
    tgemm_k<128,2,0,false><<<dim3(NP/128, 1024/128, BB), blk>>>(1024, NP, 512, 512,
        wf, 0, feats, (size_t)512*NP, hf, (size_t)1024*NP,
        nullptr, 0, bnf_g, bnf_b, INV, nullptr, 0, nullptr, 0, 0.2f);

    pool_k<<<BB * 1024, blk>>>(hf, xmax, xavg);
    r1_k<<<(BB * 512 + 255) / 256, blk>>>(ws1, bs1, xmax, xavg, r1);

    // ws1 (first 1024 input channels of 3072; pooled part folded into r1)  [tf32]
    tgemm_k<128,1,0,false><<<dim3(NP/128, 512/128, BB), blk>>>(512, NP, 1024, 3072,
        ws1, 0, hf, (size_t)1024*NP, s1, (size_t)512*NP,
        r1, 512, bns1_g, bns1_b, INV, nullptr, 0, nullptr, 0, 0.f);

    // ws2: 512 -> 256, bn + relu  [tf32]
    tgemm_k<128,1,0,false><<<dim3(NP/128, 256/128, BB), blk>>>(256, NP, 512, 512,
        ws2, 0, s1, (size_t)512*NP, s2, (size_t)256*NP,
        bs2, 0, bns2_g, bns2_b, INV, nullptr, 0, nullptr, 0, 0.f);

    // ws3 + log_softmax + transpose
    final_k<<<(BB * NP) / 256, blk>>>(s2, ws3, bs3, out);
}

// round 6
// speedup vs baseline: 2.6303x; 1.0605x over previous
#include <cuda_runtime.h>
#include <cstdint>

#define NP 4096
#define BB 2

// ---------------- scratch (static device globals; no allocation) ----------------
__device__ float g_c1[BB*128*NP];
__device__ float g_h0[BB*128*NP];
__device__ float g_qhi[BB*32*NP];
__device__ float g_qlo[BB*32*NP];
__device__ float g_v [BB*128*NP];
__device__ float g_u [BB*128*NP];
__device__ float g_rowm[BB*NP];
__device__ float g_rowsinv[BB*NP];
__device__ float g_rowm_p[2*BB*NP];
__device__ float g_rows_p[2*BB*NP];
__device__ float g_feats[BB*512*NP];
__device__ float g_hf[BB*1024*NP];
__device__ float g_xmax[BB*1024];
__device__ float g_xavg[BB*1024];
__device__ float g_r1[BB*512];
__device__ float g_s1[BB*512*NP];
__device__ float g_s2[BB*256*NP];

// ---------------- PTX helpers ----------------
__device__ __forceinline__ uint32_t smem_u32(const void* p) {
    return (uint32_t)__cvta_generic_to_shared(p);
}
__device__ __forceinline__ void cpa16(uint32_t s, const void* g) {
    asm volatile("cp.async.cg.shared.global [%0], [%1], 16;" :: "r"(s), "l"(g));
}
__device__ __forceinline__ void cpa_commit() { asm volatile("cp.async.commit_group;"); }
__device__ __forceinline__ void cpa_wait0()  { asm volatile("cp.async.wait_group 0;"); }
__device__ __forceinline__ uint32_t f2tf(float f) {
    uint32_t r;
    asm("cvt.rna.tf32.f32 %0, %1;" : "=r"(r) : "f"(f));
    return r;
}
__device__ __forceinline__ void split_tf(float x, uint32_t& hi, uint32_t& lo) {
    hi = f2tf(x);
    lo = f2tf(x - __uint_as_float(hi));
}
__device__ __forceinline__ void mma_tf32(float* c, const uint32_t* a, const uint32_t* b) {
    asm volatile(
        "mma.sync.aligned.m16n8k8.row.col.f32.tf32.tf32.f32 "
        "{%0,%1,%2,%3}, {%4,%5,%6,%7}, {%8,%9}, {%0,%1,%2,%3};"
        : "+f"(c[0]), "+f"(c[1]), "+f"(c[2]), "+f"(c[3])
        : "r"(a[0]), "r"(a[1]), "r"(a[2]), "r"(a[3]), "r"(b[0]), "r"(b[1]));
}

// =====================================================================
// PASS 1: flash row stats over half the j-range per block.
// q supplied pre-split (qhi/qlo are tf32-representable) -> no cvt in loop.
// =====================================================================
#define STATS_SMEM_FLOATS 15872
__global__ __launch_bounds__(256) void attn_stats_k(
    const float* __restrict__ qhi, const float* __restrict__ qlo,
    float* __restrict__ rowm_p, float* __restrict__ rows_p)
{
    constexpr int QS = 72;
    extern __shared__ __align__(16) float sm[];
    float* qih = sm;                 // 2304
    float* qil = sm + 2304;          // 2304
    float* qjh = sm + 4608;          // [2][2304]
    float* qjl = sm + 9216;          // [2][2304]
    float* red_m = sm + 13824;       // 1024
    float* red_s = sm + 14848;       // 1024

    const int b = blockIdx.y;
    const int i0 = blockIdx.x * 64;
    const int jh = blockIdx.z;       // 0/1 j-half
    const float* qhb = qhi + (size_t)b * 32 * NP;
    const float* qlb = qlo + (size_t)b * 32 * NP;
    const int tid = threadIdx.x;
    const int wid = tid >> 5, lane = tid & 31;
    const int lr = lane >> 2, lc = lane & 3;
    const int wi = wid >> 2;
    const int wj = wid & 3;

    for (int t = tid; t < 512; t += 256) {
        int r = t >> 4, s4 = (t & 15) * 4;
        *(float4*)&qih[r * QS + s4] = *(const float4*)&qhb[(size_t)r * NP + i0 + s4];
        *(float4*)&qil[r * QS + s4] = *(const float4*)&qlb[(size_t)r * NP + i0 + s4];
    }
    const int jbase = jh * 32;       // tile index offset
    for (int t = tid; t < 512; t += 256) {
        int r = t >> 4, s4 = (t & 15) * 4;
        cpa16(smem_u32(&qjh[r * QS + s4]), qhb + (size_t)r * NP + jbase * 64 + s4);
        cpa16(smem_u32(&qjl[r * QS + s4]), qlb + (size_t)r * NP + jbase * 64 + s4);
    }
    cpa_commit();

    float m_t[4], s_t[4];
    #pragma unroll
    for (int k = 0; k < 4; k++) { m_t[k] = -1e30f; s_t[k] = 0.f; }

    for (int jt = 0; jt < 32; jt++) {
        cpa_wait0(); __syncthreads();
        int buf = jt & 1;
        if (jt + 1 < 32) {
            int j0n = (jbase + jt + 1) * 64;
            for (int t = tid; t < 512; t += 256) {
                int r = t >> 4, s4 = (t & 15) * 4;
                cpa16(smem_u32(&qjh[(buf ^ 1) * 2304 + r * QS + s4]), qhb + (size_t)r * NP + j0n + s4);
                cpa16(smem_u32(&qjl[(buf ^ 1) * 2304 + r * QS + s4]), qlb + (size_t)r * NP + j0n + s4);
            }
            cpa_commit();
        }
        const float* jhp = qjh + buf * 2304;
        const float* jlp = qjl + buf * 2304;

        float acc[2][2][4];
        #pragma unroll
        for (int a = 0; a < 2; a++)
            #pragma unroll
            for (int c = 0; c < 2; c++)
                #pragma unroll
                for (int e = 0; e < 4; e++) acc[a][c][e] = 0.f;

        #pragma unroll
        for (int ks = 0; ks < 4; ks++) {
            int k = ks * 8 + lc;
            uint32_t ah[2][4], al[2][4];
            #pragma unroll
            for (int mt = 0; mt < 2; mt++) {
                int ib = wi * 32 + mt * 16 + lr;
                ah[mt][0] = __float_as_uint(qih[k * QS + ib]);
                ah[mt][1] = __float_as_uint(qih[k * QS + ib + 8]);
                ah[mt][2] = __float_as_uint(qih[(k + 4) * QS + ib]);
                ah[mt][3] = __float_as_uint(qih[(k + 4) * QS + ib + 8]);
                al[mt][0] = __float_as_uint(qil[k * QS + ib]);
                al[mt][1] = __float_as_uint(qil[k * QS + ib + 8]);
                al[mt][2] = __float_as_uint(qil[(k + 4) * QS + ib]);
                al[mt][3] = __float_as_uint(qil[(k + 4) * QS + ib + 8]);
            }
            uint32_t bh[2][2], bl[2][2];
            #pragma unroll
            for (int nt = 0; nt < 2; nt++) {
                int jb = wj * 16 + nt * 8 + lr;
                bh[nt][0] = __float_as_uint(jhp[k * QS + jb]);
                bh[nt][1] = __float_as_uint(jhp[(k + 4) * QS + jb]);
                bl[nt][0] = __float_as_uint(jlp[k * QS + jb]);
                bl[nt][1] = __float_as_uint(jlp[(k + 4) * QS + jb]);
            }
            #pragma unroll
            for (int mt = 0; mt < 2; mt++)
                #pragma unroll
                for (int nt = 0; nt < 2; nt++) {
                    mma_tf32(acc[mt][nt], ah[mt], bh[nt]);
                    mma_tf32(acc[mt][nt], ah[mt], bl[nt]);
                    mma_tf32(acc[mt][nt], al[mt], bh[nt]);
                }
        }
        #pragma unroll
        for (int mt = 0; mt < 2; mt++) {
            #pragma unroll
            for (int half = 0; half < 2; half++) {
                int idx = mt * 2 + half;
                float v0 = acc[mt][0][half * 2], v1 = acc[mt][0][half * 2 + 1];
                float v2 = acc[mt][1][half * 2], v3 = acc[mt][1][half * 2 + 1];
                float tmax = fmaxf(fmaxf(v0, v1), fmaxf(v2, v3));
                float mnew = fmaxf(m_t[idx], tmax);
                float sc = __expf(m_t[idx] - mnew);
                float add = __expf(v0 - mnew) + __expf(v1 - mnew)
                          + __expf(v2 - mnew) + __expf(v3 - mnew);
                s_t[idx] = s_t[idx] * sc + add;
                m_t[idx] = mnew;
            }
        }
    }
    #pragma unroll
    for (int mt = 0; mt < 2; mt++)
        #pragma unroll
        for (int half = 0; half < 2; half++) {
            int row = wi * 32 + mt * 16 + half * 8 + lr;
            int slot = wj * 4 + lc;
            red_m[row * 16 + slot] = m_t[mt * 2 + half];
            red_s[row * 16 + slot] = s_t[mt * 2 + half];
        }
    __syncthreads();
    if (tid < 64) {
        float mt_ = -1e30f;
        #pragma unroll
        for (int k = 0; k < 16; k++) mt_ = fmaxf(mt_, red_m[tid * 16 + k]);
        float s = 0.f;
        #pragma unroll
        for (int k = 0; k < 16; k++)
            s += red_s[tid * 16 + k] * __expf(red_m[tid * 16 + k] - mt_);
        size_t p = ((size_t)jh * BB + b) * NP + i0 + tid;
        rowm_p[p] = mt_;
        rows_p[p] = s;
    }
}

// merge the two j-half partials
__global__ void stats_merge_k(const float* __restrict__ mp, const float* __restrict__ sp,
                              float* __restrict__ rowm, float* __restrict__ rowsinv)
{
    int i = blockIdx.x * 256 + threadIdx.x;    // BB*NP
    float m0 = mp[i], m1 = mp[BB * NP + i];
    float s0 = sp[i], s1 = sp[BB * NP + i];
    float m = fmaxf(m0, m1);
    float s = s0 * __expf(m0 - m) + s1 * __expf(m1 - m);
    rowm[i] = m;
    rowsinv[i] = 1.f / s;
}

// =====================================================================
// PASS 2: fused energy->softmax->colsum->v@attn->residual.
// q pre-split, v pre-rounded to tf32 -> no cvt on fragment loads.
// =====================================================================
#define FUSE_SMEM_FLOATS 37952
__global__ __launch_bounds__(256) void attn_fuse_k(
    const float* __restrict__ qhi, const float* __restrict__ qlo,
    const float* __restrict__ v,
    const float* __restrict__ rowm, const float* __restrict__ rowsinv,
    const float* __restrict__ hin, size_t sHin,
    float* __restrict__ u)
{
    extern __shared__ __align__(16) float sm[];
    float* qjh = sm;                  // 2304
    float* qjl = sm + 2304;           // 2304
    float* qih = sm + 4608;           // [2][2304]
    float* qil = sm + 9216;           // [2][2304]
    float* v_s = sm + 13824;          // [2][9728]
    float* at_s = sm + 33280;         // [64][72]
    float* cs_s = sm + 37888;         // 64

    const int b = blockIdx.y;
    const int n0 = blockIdx.x * 64;
    const float* qhb = qhi + (size_t)b * 32 * NP;
    const float* qlb = qlo + (size_t)b * 32 * NP;
    const float* vb = v + (size_t)b * 128 * NP;
    const int tid = threadIdx.x;
    const int wid = tid >> 5, lane = tid & 31;
    const int lr = lane >> 2, lc = lane & 3;
    const int w1 = wid >> 1;      // 0..3
    const int w2 = wid & 1;       // 0..1

    if (tid < 64) cs_s[tid] = 0.f;

    for (int t = tid; t < 512; t += 256) {
        int r = t >> 4, s4 = (t & 15) * 4;
        cpa16(smem_u32(qjh + r * 72 + s4), qhb + (size_t)r * NP + n0 + s4);
        cpa16(smem_u32(qjl + r * 72 + s4), qlb + (size_t)r * NP + n0 + s4);
        cpa16(smem_u32(qih + r * 72 + s4), qhb + (size_t)r * NP + s4);
        cpa16(smem_u32(qil + r * 72 + s4), qlb + (size_t)r * NP + s4);
    }
    for (int t = tid; t < 2048; t += 256) {
        int r = t >> 4, s4 = (t & 15) * 4;
        cpa16(smem_u32(v_s + r * 76 + s4), vb + (size_t)r * NP + s4);
    }
    cpa_commit();

    float acc_v[2][4][4];
    #pragma unroll
    for (int a = 0; a < 2; a++)
        #pragma unroll
        for (int c = 0; c < 4; c++)
            #pragma unroll
            for (int e = 0; e < 4; e++) acc_v[a][c][e] = 0.f;
    float cs_part[8];
    #pragma unroll
    for (int p = 0; p < 8; p++) cs_part[p] = 0.f;

    for (int it = 0; it < 64; it++) {
        cpa_wait0(); __syncthreads();
        int buf = it & 1;
        if (it + 1 < 64) {
            int i0n = (it + 1) * 64;
            for (int t = tid; t < 512; t += 256) {
                int r = t >> 4, s4 = (t & 15) * 4;
                cpa16(smem_u32(qih + (buf ^ 1) * 2304 + r * 72 + s4), qhb + (size_t)r * NP + i0n + s4);
                cpa16(smem_u32(qil + (buf ^ 1) * 2304 + r * 72 + s4), qlb + (size_t)r * NP + i0n + s4);
            }
            for (int t = tid; t < 2048; t += 256) {
                int r = t >> 4, s4 = (t & 15) * 4;
                cpa16(smem_u32(v_s + (buf ^ 1) * 9728 + r * 76 + s4), vb + (size_t)r * NP + i0n + s4);
            }
            cpa_commit();
        }
        const int i0 = it * 64;
        const float* qiph = qih + buf * 2304;
        const float* qipl = qil + buf * 2304;
        const float* vp   = v_s + buf * 9728;

        // ---- phase e: 64i x 64j; warp tile 16i x 32j ----
        float ae[4][4];
        #pragma unroll
        for (int c = 0; c < 4; c++)
            #pragma unroll
            for (int e = 0; e < 4; e++) ae[c][e] = 0.f;
        #pragma unroll
        for (int ks = 0; ks < 4; ks++) {
            int k = ks * 8 + lc;
            int ib = w1 * 16 + lr;
            uint32_t ah[4], al[4];
            ah[0] = __float_as_uint(qiph[k * 72 + ib]);
            ah[1] = __float_as_uint(qiph[k * 72 + ib + 8]);
            ah[2] = __float_as_uint(qiph[(k + 4) * 72 + ib]);
            ah[3] = __float_as_uint(qiph[(k + 4) * 72 + ib + 8]);
            al[0] = __float_as_uint(qipl[k * 72 + ib]);
            al[1] = __float_as_uint(qipl[k * 72 + ib + 8]);
            al[2] = __float_as_uint(qipl[(k + 4) * 72 + ib]);
            al[3] = __float_as_uint(qipl[(k + 4) * 72 + ib + 8]);
            #pragma unroll
            for (int nt = 0; nt < 4; nt++) {
                int jb = w2 * 32 + nt * 8 + lr;
                uint32_t bh[2], bl[2];
                bh[0] = __float_as_uint(qjh[k * 72 + jb]);
                bh[1] = __float_as_uint(qjh[(k + 4) * 72 + jb]);
                bl[0] = __float_as_uint(qjl[k * 72 + jb]);
                bl[1] = __float_as_uint(qjl[(k + 4) * 72 + jb]);
                mma_tf32(ae[nt], ah, bh);
                mma_tf32(ae[nt], ah, bl);
                mma_tf32(ae[nt], al, bh);
            }
        }
        // exp + store tf32-rounded attn tile + colsum partials (unrounded)
        {
            int gi = b * NP + i0 + w1 * 16 + lr;
            float m0 = rowm[gi],     m1 = rowm[gi + 8];
            float si0 = rowsinv[gi], si1 = rowsinv[gi + 8];
            #pragma unroll
            for (int nt = 0; nt < 4; nt++) {
                float e00 = __expf(ae[nt][0] - m0) * si0;
                float e01 = __expf(ae[nt][1] - m0) * si0;
                float e10 = __expf(ae[nt][2] - m1) * si1;
                float e11 = __expf(ae[nt][3] - m1) * si1;
                int jb = w2 * 32 + nt * 8 + lc * 2;
                int ib = w1 * 16 + lr;
                *(float2*)&at_s[ib * 72 + jb] =
                    make_float2(__uint_as_float(f2tf(e00)), __uint_as_float(f2tf(e01)));
                *(float2*)&at_s[(ib + 8) * 72 + jb] =
                    make_float2(__uint_as_float(f2tf(e10)), __uint_as_float(f2tf(e11)));
                cs_part[nt * 2]     += e00 + e10;
                cs_part[nt * 2 + 1] += e01 + e11;
            }
        }
        __syncthreads();

        // ---- phase v: 128c x 64j, K=64; warp tile 32c x 32j ----
        #pragma unroll
        for (int ks = 0; ks < 8; ks++) {
            int k = ks * 8 + lc;
            uint32_t av[2][4];
            #pragma unroll
            for (int mt = 0; mt < 2; mt++) {
                int cb = w1 * 32 + mt * 16 + lr;
                av[mt][0] = __float_as_uint(vp[cb * 76 + k]);
                av[mt][1] = __float_as_uint(vp[(cb + 8) * 76 + k]);
                av[mt][2] = __float_as_uint(vp[cb * 76 + k + 4]);
                av[mt][3] = __float_as_uint(vp[(cb + 8) * 76 + k + 4]);
            }
            #pragma unroll
            for (int nt = 0; nt < 4; nt++) {
                int jb = w2 * 32 + nt * 8 + lr;
                uint32_t bv[2];
                bv[0] = __float_as_uint(at_s[k * 72 + jb]);
                bv[1] = __float_as_uint(at_s[(k + 4) * 72 + jb]);
                #pragma unroll
                for (int mt = 0; mt < 2; mt++)
                    mma_tf32(acc_v[mt][nt], av[mt], bv);
            }
        }
    }

    #pragma unroll
    for (int p = 0; p < 8; p++) {
        int jb = w2 * 32 + (p >> 1) * 8 + lc * 2 + (p & 1);
        atomicAdd(&cs_s[jb], cs_part[p]);
    }
    __syncthreads();
    if (tid < 64) cs_s[tid] = 1.f / (1e-9f + cs_s[tid]);
    __syncthreads();

    #pragma unroll
    for (int mt = 0; mt < 2; mt++) {
        #pragma unroll
        for (int half = 0; half < 2; half++) {
            int c = w1 * 32 + mt * 16 + half * 8 + lr;
            #pragma unroll
            for (int nt = 0; nt < 4; nt++) {
                int jb = w2 * 32 + nt * 8 + lc * 2;
                float ci0 = cs_s[jb], ci1 = cs_s[jb + 1];
                float2 hv = *(const float2*)&hin[(size_t)b * sHin + (size_t)c * NP + n0 + jb];
                float2 o;
                o.x = hv.x - acc_v[mt][nt][half * 2]     * ci0;
                o.y = hv.y - acc_v[mt][nt][half * 2 + 1] * ci1;
                *(float2*)&u[(size_t)b * 128 * NP + (size_t)c * NP + n0 + jb] = o;
            }
        }
    }
}

// ---------------- tf32 tensor-core GEMM with fused epilogues ----------------
template<int BN>
__device__ __forceinline__ void t_load(float* As, float* Bs,
    const float* __restrict__ Ab, const float* __restrict__ Bb,
    int tid, int kt, int lda, int N)
{
    constexpr int ASTR = 20;
    constexpr int BSTR = BN + 8;
    #pragma unroll
    for (int i = 0; i < 2; i++) {
        int idx = tid + i * 256;
        int row = idx >> 2, seg = (idx & 3) * 4;
        cpa16(smem_u32(As + row * ASTR + seg), Ab + (size_t)row * lda + kt * 16 + seg);
    }
    constexpr int BF4 = BN / 64;
    #pragma unroll
    for (int i = 0; i < BF4; i++) {
        int idx = tid + i * 256;
        int row = idx / (BN / 4), seg = (idx % (BN / 4)) * 4;
        cpa16(smem_u32(Bs + row * BSTR + seg), Bb + (size_t)(kt * 16 + row) * N + seg);
    }
}

template<int BN, int ACT, int RES, bool COLDIV>
__global__ __launch_bounds__(256) void tgemm_k(int M, int N, int K, int lda,
    const float* __restrict__ A, size_t sA,
    const float* __restrict__ B, size_t sB,
    float* __restrict__ C, size_t sC,
    const float* __restrict__ rb, size_t sRB,
    const float* __restrict__ bng, const float* __restrict__ bnb, float bninv,
    const float* __restrict__ res, size_t sRes,
    const float* __restrict__ cs, size_t sCS,
    float slope)
{
    constexpr int BM = 128, BK = 16;
    constexpr int ASTR = 20;
    constexpr int BSTR = BN + 8;
    constexpr int WN = BN / 4;
    constexpr int NT = WN / 8;
    __shared__ __align__(16) float As[2][BM * ASTR];
    __shared__ __align__(16) float Bs[2][BK * BSTR];

    const int b = blockIdx.z;
    const int m0 = blockIdx.y * BM, n0 = blockIdx.x * BN;
    const float* Ab = A + (size_t)b * sA + (size_t)m0 * lda;
    const float* Bb = B + (size_t)b * sB + n0;
    const int tid = threadIdx.x;
    const int wid = tid >> 5, lane = tid & 31;
    const int wm = wid >> 2, wn = wid & 3;
    const int lr = lane >> 2, lc = lane & 3;

    float acc[4][NT][4];
    #pragma unroll
    for (int i = 0; i < 4; i++)
        #pragma unroll
        for (int j = 0; j < NT; j++)
            #pragma unroll
            for (int e = 0; e < 4; e++) acc[i][j][e] = 0.f;

    const int nk = K / BK;
    t_load<BN>(As[0], Bs[0], Ab, Bb, tid, 0, lda, N);
    cpa_commit();

    for (int kt = 0; kt < nk; kt++) {
        cpa_wait0();
        __syncthreads();
        int buf = kt & 1;
        if (kt + 1 < nk) {
            t_load<BN>(As[buf ^ 1], Bs[buf ^ 1], Ab, Bb, tid, kt + 1, lda, N);
            cpa_commit();
        }
        #pragma unroll
        for (int ks = 0; ks < 2; ks++) {
            const float* Ap = &As[buf][0];
            const float* Bp = &Bs[buf][0];
            uint32_t af[4][4];
            #pragma unroll
            for (int mt = 0; mt < 4; mt++) {
                int r = wm * 64 + mt * 16 + lr;
                int c = ks * 8 + lc;
                af[mt][0] = f2tf(Ap[(r    ) * ASTR + c    ]);
                af[mt][1] = f2tf(Ap[(r + 8) * ASTR + c    ]);
                af[mt][2] = f2tf(Ap[(r    ) * ASTR + c + 4]);
                af[mt][3] = f2tf(Ap[(r + 8) * ASTR + c + 4]);
            }
            uint32_t bf[NT][2];
            #pragma unroll
            for (int nt = 0; nt < NT; nt++) {
                int cgl = wn * WN + nt * 8 + lr;
                int k = ks * 8 + lc;
                bf[nt][0] = f2tf(Bp[(k    ) * BSTR + cgl]);
                bf[nt][1] = f2tf(Bp[(k + 4) * BSTR + cgl]);
            }
            #pragma unroll
            for (int mt = 0; mt < 4; mt++)
                #pragma unroll
                for (int nt = 0; nt < NT; nt++)
                    mma_tf32(acc[mt][nt], af[mt], bf[nt]);
        }
        __syncthreads();
    }

    #pragma unroll
    for (int mt = 0; mt < 4; mt++) {
        #pragma unroll
        for (int h = 0; h < 2; h++) {
            int mm = m0 + wm * 64 + mt * 16 + h * 8 + lr;
            float scale = (bng ? bng[mm] : 1.f) * bninv;
            float shift = bnb ? bnb[mm] : 0.f;
            float rbv   = rb  ? rb[(size_t)b * sRB + mm] : 0.f;
            #pragma unroll
            for (int nt = 0; nt < NT; nt++) {
                int n = n0 + wn * WN + nt * 8 + lc * 2;
                float v0 = acc[mt][nt][h * 2 + 0];
                float v1 = acc[mt][nt][h * 2 + 1];
                if (COLDIV) {
                    v0 = v0 / (1e-9f + cs[(size_t)b * sCS + n]);
                    v1 = v1 / (1e-9f + cs[(size_t)b * sCS + n + 1]);
                }
                v0 = (v0 + rbv) * scale + shift;
                v1 = (v1 + rbv) * scale + shift;
                if (ACT == 1) { v0 = fmaxf(v0, 0.f); v1 = fmaxf(v1, 0.f); }
                else if (ACT == 2) { v0 = v0 > 0.f ? v0 : slope * v0; v1 = v1 > 0.f ? v1 : slope * v1; }
                if (RES == 1) {
                    v0 = res[(size_t)b * sRes + (size_t)mm * N + n] + v0;
                    v1 = res[(size_t)b * sRes + (size_t)mm * N + n + 1] + v1;
                } else if (RES == 2) {
                    v0 = res[(size_t)b * sRes + (size_t)mm * N + n] - v0;
                    v1 = res[(size_t)b * sRes + (size_t)mm * N + n + 1] - v1;
                }
                *(float2*)&C[(size_t)b * sC + (size_t)mm * N + n] = make_float2(v0, v1);
            }
        }
    }
}

// ---------------- fp32 tiled SGEMM with fused epilogues (small GEMMs) ----------------
// OMODE: 0 = normal fp32 out, 1 = write tf32 hi to C and lo to C2, 2 = tf32-rounded out
template<bool TA, int ACT, int RES, bool COLDIV, int OMODE>
__global__ void gemm_k(int M, int N, int K, int lda,
    const float* __restrict__ A, size_t sA,
    const float* __restrict__ B, size_t sB,
    float* __restrict__ C, float* __restrict__ C2, size_t sC,
    const float* __restrict__ rb, size_t sRB,
    const float* __restrict__ bng, const float* __restrict__ bnb, float bninv,
    const float* __restrict__ res, size_t sRes,
    float slope)
{
    __shared__ float As[16][68];
    __shared__ float Bs[16][68];
    const int b  = blockIdx.z;
    const float* Ab = A + (size_t)b * sA;
    const float* Bb = B + (size_t)b * sB;
    const int m0 = blockIdx.y * 64;
    const int n0 = blockIdx.x * 64;
    const int tid = threadIdx.x;
    const int tx = tid & 15, ty = tid >> 4;

    float acc[4][4];
    #pragma unroll
    for (int i = 0; i < 4; i++)
        #pragma unroll
        for (int j = 0; j < 4; j++) acc[i][j] = 0.f;

    for (int k0 = 0; k0 < K; k0 += 16) {
        if (TA) {
            int kk = tid >> 4, mq = tid & 15;
            float4 av = *(const float4*)&Ab[(size_t)(k0 + kk) * lda + m0 + mq * 4];
            *(float4*)&As[kk][mq * 4] = av;
        } else {
            int m = tid >> 2, kq = tid & 3;
            float4 av = make_float4(0.f, 0.f, 0.f, 0.f);
            if (m0 + m < M)
                av = *(const float4*)&Ab[(size_t)(m0 + m) * lda + k0 + kq * 4];
            As[kq * 4 + 0][m] = av.x;
            As[kq * 4 + 1][m] = av.y;
            As[kq * 4 + 2][m] = av.z;
            As[kq * 4 + 3][m] = av.w;
        }
        {
            int kk = tid >> 4, nq = tid & 15;
            float4 bv = *(const float4*)&Bb[(size_t)(k0 + kk) * N + n0 + nq * 4];
            *(float4*)&Bs[kk][nq * 4] = bv;
        }
        __syncthreads();
        #pragma unroll
        for (int k = 0; k < 16; k++) {
            float4 a4 = *(float4*)&As[k][ty * 4];
            float4 b4 = *(float4*)&Bs[k][tx * 4];
            float ar[4] = {a4.x, a4.y, a4.z, a4.w};
            float br[4] = {b4.x, b4.y, b4.z, b4.w};
            #pragma unroll
            for (int i = 0; i < 4; i++)
                #pragma unroll
                for (int j = 0; j < 4; j++)
                    acc[i][j] = fmaf(ar[i], br[j], acc[i][j]);
        }
        __syncthreads();
    }

    #pragma unroll
    for (int i = 0; i < 4; i++) {
        int m = m0 + ty * 4 + i;
        if (m >= M) continue;
        float scale = (bng ? bng[m] : 1.f) * bninv;
        float shift = bnb ? bnb[m] : 0.f;
        float rbv   = rb  ? rb[(size_t)b * sRB + m] : 0.f;
        #pragma unroll
        for (int j = 0; j < 4; j++) {
            int n = n0 + tx * 4 + j;
            float v = acc[i][j];
            v = (v + rbv) * scale + shift;
            if (ACT == 1) v = fmaxf(v, 0.f);
            else if (ACT == 2) v = v > 0.f ? v : slope * v;
            if (RES == 1)      v = res[(size_t)b * sRes + (size_t)m * N + n] + v;
            else if (RES == 2) v = res[(size_t)b * sRes + (size_t)m * N + n] - v;
            size_t off = (size_t)b * sC + (size_t)m * N + n;
            if (OMODE == 1) {
                uint32_t hi, lo; split_tf(v, hi, lo);
                C[off]  = __uint_as_float(hi);
                C2[off] = __uint_as_float(lo);
            } else if (OMODE == 2) {
                C[off] = __uint_as_float(f2tf(v));
            } else {
                C[off] = v;
            }
        }
    }
}

// ---------------- conv1 ----------------
__global__ void conv1_k(const float* __restrict__ x, const float* __restrict__ w1,
                        const float* __restrict__ g, const float* __restrict__ bb,
                        float inv, float* __restrict__ out)
{
    int idx = blockIdx.x * blockDim.x + threadIdx.x;
    int n = idx & (NP - 1);
    int o = (idx / NP) & 127;
    int b = idx / (128 * NP);
    const float* xp = x + ((size_t)b * 15 + 9) * NP + n;
    float s = w1[o * 3 + 0] * xp[0] + w1[o * 3 + 1] * xp[NP] + w1[o * 3 + 2] * xp[2 * NP];
    s = s * g[o] * inv + bb[o];
    out[idx] = fmaxf(s, 0.f);
}

// ---------------- global max/mean pooling over N ----------------
__global__ void pool_k(const float* __restrict__ hf, float* __restrict__ xmax, float* __restrict__ xavg)
{
    int bc = blockIdx.x;
    const float* p = hf + (size_t)bc * NP;
    int t = threadIdx.x;
    float mx = -1e30f, sm = 0.f;
    for (int i = t; i < NP; i += 256) { float v = p[i]; mx = fmaxf(mx, v); sm += v; }
    __shared__ float rm[256], rs[256];
    rm[t] = mx; rs[t] = sm; __syncthreads();
    for (int s = 128; s > 0; s >>= 1) {
        if (t < s) { rm[t] = fmaxf(rm[t], rm[t + s]); rs[t] += rs[t + s]; }
        __syncthreads();
    }
    if (t == 0) { xmax[bc] = rm[0]; xavg[bc] = rs[0] * (1.f / NP); }
}

// ---------------- fold pooled channels of ws1 into per-row bias ----------------
__global__ void r1_k(const float* __restrict__ ws1, const float* __restrict__ bs1,
                     const float* __restrict__ xmax, const float* __restrict__ xavg,
                     float* __restrict__ r1)
{
    int idx = blockIdx.x * blockDim.x + threadIdx.x;
    if (idx >= BB * 512) return;
    int b = idx / 512, o = idx % 512;
    const float* w = ws1 + (size_t)o * 3072;
    float s = bs1[o];
    #pragma unroll 4
    for (int c = 0; c < 1024; c++)
        s += w[1024 + c] * xmax[b * 1024 + c] + w[2048 + c] * xavg[b * 1024 + c];
    r1[idx] = s;
}

// ---------------- ws3 (8x256) + log_softmax + transpose ----------------
__global__ void final_k(const float* __restrict__ s2, const float* __restrict__ ws3,
                        const float* __restrict__ bs3, float* __restrict__ out)
{
    __shared__ float w[8 * 256];
    __shared__ float bias[8];
    int t = threadIdx.x;
    for (int i = t; i < 2048; i += blockDim.x) w[i] = ws3[i];
    if (t < 8) bias[t] = bs3[t];
    __syncthreads();
    int idx = blockIdx.x * blockDim.x + t;
    int b = idx / NP, n = idx & (NP - 1);
    const float* sp = s2 + (size_t)b * 256 * NP + n;
    float l[8];
    #pragma unroll
    for (int k = 0; k < 8; k++) l[k] = bias[k];
    for (int c = 0; c < 256; c++) {
        float v = sp[(size_t)c * NP];
        #pragma unroll
        for (int k = 0; k < 8; k++) l[k] = fmaf(w[k * 256 + c], v, l[k]);
    }
    float m = l[0];
    #pragma unroll
    for (int k = 1; k < 8; k++) m = fmaxf(m, l[k]);
    float s = 0.f;
    #pragma unroll
    for (int k = 0; k < 8; k++) s += expf(l[k] - m);
    float lse = m + logf(s);
    #pragma unroll
    for (int k = 0; k < 8; k++)
        out[((size_t)b * NP + n) * 8 + k] = l[k] - lse;
}

// ---------------- host launch ----------------
extern "C" void kernel_launch(void* const* d_in, const int* in_sizes, int n_in,
                              void* d_out, int out_size)
{
    const float* x      = (const float*)d_in[0];
    const float* w1     = (const float*)d_in[1];
    const float* bn1_g  = (const float*)d_in[2];
    const float* bn1_b  = (const float*)d_in[3];
    const float* w2     = (const float*)d_in[4];
    const float* bn2_g  = (const float*)d_in[5];
    const float* bn2_b  = (const float*)d_in[6];
    const float* sa_wqk = (const float*)d_in[7];
    const float* sa_wv  = (const float*)d_in[8];
    const float* sa_bv  = (const float*)d_in[9];
    const float* sa_wt  = (const float*)d_in[10];
    const float* sa_bt  = (const float*)d_in[11];
    const float* sa_bng = (const float*)d_in[12];
    const float* sa_bnb = (const float*)d_in[13];
    const float* wf     = (const float*)d_in[14];
    const float* bnf_g  = (const float*)d_in[15];
    const float* bnf_b  = (const float*)d_in[16];
    const float* ws1    = (const float*)d_in[17];
    const float* bs1    = (const float*)d_in[18];
    const float* bns1_g = (const float*)d_in[19];
    const float* bns1_b = (const float*)d_in[20];
    const float* ws2    = (const float*)d_in[21];
    const float* bs2    = (const float*)d_in[22];
    const float* bns2_g = (const float*)d_in[23];
    const float* bns2_b = (const float*)d_in[24];
    const float* ws3    = (const float*)d_in[25];
    const float* bs3    = (const float*)d_in[26];
    float* out = (float*)d_out;

    float *c1, *h0, *qhi, *qlo, *v, *u, *rowm, *rowsinv, *rowm_p, *rows_p;
    float *feats, *hf, *xmax, *xavg, *r1, *s1, *s2;
    cudaGetSymbolAddress((void**)&c1,      g_c1);
    cudaGetSymbolAddress((void**)&h0,      g_h0);
    cudaGetSymbolAddress((void**)&qhi,     g_qhi);
    cudaGetSymbolAddress((void**)&qlo,     g_qlo);
    cudaGetSymbolAddress((void**)&v,       g_v);
    cudaGetSymbolAddress((void**)&u,       g_u);
    cudaGetSymbolAddress((void**)&rowm,    g_rowm);
    cudaGetSymbolAddress((void**)&rowsinv, g_rowsinv);
    cudaGetSymbolAddress((void**)&rowm_p,  g_rowm_p);
    cudaGetSymbolAddress((void**)&rows_p,  g_rows_p);
    cudaGetSymbolAddress((void**)&feats,   g_feats);
    cudaGetSymbolAddress((void**)&hf,      g_hf);
    cudaGetSymbolAddress((void**)&xmax,    g_xmax);
    cudaGetSymbolAddress((void**)&xavg,    g_xavg);
    cudaGetSymbolAddress((void**)&r1,      g_r1);
    cudaGetSymbolAddress((void**)&s1,      g_s1);
    cudaGetSymbolAddress((void**)&s2,      g_s2);

    const float INV = 0.999995000037499219f;   // 1/sqrt(1 + 1e-5)
    dim3 blk(256);
    const int STATS_SMEM = STATS_SMEM_FLOATS * 4;
    const int FUSE_SMEM  = FUSE_SMEM_FLOATS * 4;
    cudaFuncSetAttribute(attn_stats_k, cudaFuncAttributeMaxDynamicSharedMemorySize, STATS_SMEM);
    cudaFuncSetAttribute(attn_fuse_k,  cudaFuncAttributeMaxDynamicSharedMemorySize, FUSE_SMEM);

    // conv1: 3 -> 128, bn+relu
    conv1_k<<<(BB * 128 * NP) / 256, blk>>>(x, w1, bn1_g, bn1_b, INV, c1);

    // conv2: 128 -> 128, bn+relu
    gemm_k<false,1,0,false,0><<<dim3(NP/64, 2, BB), blk>>>(128, NP, 128, 128,
        w2, 0, c1, (size_t)128*NP, h0, nullptr, (size_t)128*NP,
        nullptr, 0, bn2_g, bn2_b, INV, nullptr, 0, 0.f);

    for (int i = 0; i < 4; i++) {
        const float* hin = (i == 0) ? h0 : feats + (size_t)(i - 1) * 128 * NP;
        size_t sHin = (i == 0) ? (size_t)128 * NP : (size_t)512 * NP;

        // q = wqk @ h  (32 x 4096) fp32 -> pre-split tf32 hi/lo
        gemm_k<false,0,0,false,1><<<dim3(NP/64, 1, BB), blk>>>(32, NP, 128, 128,
            sa_wqk + (size_t)i*32*128, 0, hin, sHin, qhi, qlo, (size_t)32*NP,
            nullptr, 0, nullptr, nullptr, 1.f, nullptr, 0, 0.f);

        // pass 1: row softmax stats (2 j-halves) + merge
        attn_stats_k<<<dim3(NP/64, BB, 2), blk, STATS_SMEM>>>(qhi, qlo, rowm_p, rows_p);
        stats_merge_k<<<(BB * NP) / 256, blk>>>(rowm_p, rows_p, rowm, rowsinv);

        // v = wv @ h + bv, stored pre-rounded to tf32
        gemm_k<false,0,0,false,2><<<dim3(NP/64, 2, BB), blk>>>(128, NP, 128, 128,
            sa_wv + (size_t)i*128*128, 0, hin, sHin, v, nullptr, (size_t)128*NP,
            sa_bv + (size_t)i*128, 0, nullptr, nullptr, 1.f, nullptr, 0, 0.f);

        // pass 2: fused energy->softmax->colsum->v@attn->residual: u = h - x_r
        attn_fuse_k<<<dim3(NP/64, BB), blk, FUSE_SMEM>>>(qhi, qlo, v, rowm, rowsinv, hin, sHin, u);

        // h_new = h + relu(bn(wt @ u + bt))  -> feats block i  (fp32)
        gemm_k<false,1,1,false,0><<<dim3(NP/64, 2, BB), blk>>>(128, NP, 128, 128,
            sa_wt + (size_t)i*128*128, 0, u, (size_t)128*NP,
            feats + (size_t)i*128*NP, nullptr, (size_t)512*NP,
            sa_bt + (size_t)i*128, 0, sa_bng + (size_t)i*128, sa_bnb + (size_t)i*128, INV,
            hin, sHin, 0.f);
    }

    // wf: 512 -> 1024, bn + leaky_relu(0.2)  [tf32 tensor]
    tgemm_k<128,2,0,false><<<dim3(NP/128, 1024/128, BB), blk>>>(1024, NP, 512, 512,
        wf, 0, feats, (size_t)512*NP, hf, (size_t)1024*NP,
        nullptr, 0, bnf_g, bnf_b, INV, nullptr, 0, nullptr, 0, 0.2f);

    pool_k<<<BB * 1024, blk>>>(hf, xmax, xavg);
    r1_k<<<(BB * 512 + 255) / 256, blk>>>(ws1, bs1, xmax, xavg, r1);

    // ws1 (first 1024 input channels of 3072; pooled part folded into r1)  [tf32]
    tgemm_k<128,1,0,false><<<dim3(NP/128, 512/128, BB), blk>>>(512, NP, 1024, 3072,
        ws1, 0, hf, (size_t)1024*NP, s1, (size_t)512*NP,
        r1, 512, bns1_g, bns1_b, INV, nullptr, 0, nullptr, 0, 0.f);

    // ws2: 512 -> 256, bn + relu  [tf32]
    tgemm_k<128,1,0,false><<<dim3(NP/128, 256/128, BB), blk>>>(256, NP, 512, 512,
        ws2, 0, s1, (size_t)512*NP, s2, (size_t)256*NP,
        bs2, 0, bns2_g, bns2_b, INV, nullptr, 0, nullptr, 0, 0.f);

    // ws3 + log_softmax + transpose
    final_k<<<(BB * NP) / 256, blk>>>(s2, ws3, bs3, out);
}

// round 8
// speedup vs baseline: 2.6914x; 1.0232x over previous
#include <cuda_runtime.h>
#include <cstdint>

#define NP 4096
#define BB 2

// ---------------- scratch (static device globals; no allocation) ----------------
__device__ float g_c1[BB*128*NP];
__device__ float g_h0[BB*128*NP];
__device__ float g_qhi[BB*32*NP];
__device__ float g_qlo[BB*32*NP];
__device__ float g_v [BB*128*NP];
__device__ float g_u [BB*128*NP];
__device__ float g_rowm[BB*NP];
__device__ float g_rowsinv[BB*NP];
__device__ float g_rowm_p[2*BB*NP];
__device__ float g_rows_p[2*BB*NP];
__device__ float g_feats[BB*512*NP];
__device__ float g_hf[BB*1024*NP];
__device__ float g_xmax[BB*1024];
__device__ float g_xavg[BB*1024];
__device__ float g_r1[BB*512];
__device__ float g_s1[BB*512*NP];
__device__ float g_s2[BB*256*NP];

// ---------------- PTX helpers ----------------
__device__ __forceinline__ uint32_t smem_u32(const void* p) {
    return (uint32_t)__cvta_generic_to_shared(p);
}
__device__ __forceinline__ void cpa16(uint32_t s, const void* g) {
    asm volatile("cp.async.cg.shared.global [%0], [%1], 16;" :: "r"(s), "l"(g));
}
__device__ __forceinline__ void cpa_commit() { asm volatile("cp.async.commit_group;"); }
__device__ __forceinline__ void cpa_wait0()  { asm volatile("cp.async.wait_group 0;"); }
__device__ __forceinline__ uint32_t f2tf(float f) {
    uint32_t r;
    asm("cvt.rna.tf32.f32 %0, %1;" : "=r"(r) : "f"(f));
    return r;
}
__device__ __forceinline__ void split_tf(float x, uint32_t& hi, uint32_t& lo) {
    hi = f2tf(x);
    lo = f2tf(x - __uint_as_float(hi));
}
__device__ __forceinline__ void mma_tf32(float* c, const uint32_t* a, const uint32_t* b) {
    asm volatile(
        "mma.sync.aligned.m16n8k8.row.col.f32.tf32.tf32.f32 "
        "{%0,%1,%2,%3}, {%4,%5,%6,%7}, {%8,%9}, {%0,%1,%2,%3};"
        : "+f"(c[0]), "+f"(c[1]), "+f"(c[2]), "+f"(c[3])
        : "r"(a[0]), "r"(a[1]), "r"(a[2]), "r"(a[3]), "r"(b[0]), "r"(b[1]));
}

// =====================================================================
// PASS 1: flash row stats over half the j-range per block.
// =====================================================================
#define STATS_SMEM_FLOATS 15872
__global__ __launch_bounds__(256) void attn_stats_k(
    const float* __restrict__ qhi, const float* __restrict__ qlo,
    float* __restrict__ rowm_p, float* __restrict__ rows_p)
{
    constexpr int QS = 72;
    extern __shared__ __align__(16) float sm[];
    float* qih = sm;                 // 2304
    float* qil = sm + 2304;          // 2304
    float* qjh = sm + 4608;          // [2][2304]
    float* qjl = sm + 9216;          // [2][2304]
    float* red_m = sm + 13824;       // 1024
    float* red_s = sm + 14848;       // 1024

    const int b = blockIdx.y;
    const int i0 = blockIdx.x * 64;
    const int jh = blockIdx.z;
    const float* qhb = qhi + (size_t)b * 32 * NP;
    const float* qlb = qlo + (size_t)b * 32 * NP;
    const int tid = threadIdx.x;
    const int wid = tid >> 5, lane = tid & 31;
    const int lr = lane >> 2, lc = lane & 3;
    const int wi = wid >> 2;
    const int wj = wid & 3;

    for (int t = tid; t < 512; t += 256) {
        int r = t >> 4, s4 = (t & 15) * 4;
        *(float4*)&qih[r * QS + s4] = *(const float4*)&qhb[(size_t)r * NP + i0 + s4];
        *(float4*)&qil[r * QS + s4] = *(const float4*)&qlb[(size_t)r * NP + i0 + s4];
    }
    const int jbase = jh * 32;
    for (int t = tid; t < 512; t += 256) {
        int r = t >> 4, s4 = (t & 15) * 4;
        cpa16(smem_u32(&qjh[r * QS + s4]), qhb + (size_t)r * NP + jbase * 64 + s4);
        cpa16(smem_u32(&qjl[r * QS + s4]), qlb + (size_t)r * NP + jbase * 64 + s4);
    }
    cpa_commit();

    float m_t[4], s_t[4];
    #pragma unroll
    for (int k = 0; k < 4; k++) { m_t[k] = -1e30f; s_t[k] = 0.f; }

    for (int jt = 0; jt < 32; jt++) {
        cpa_wait0(); __syncthreads();
        int buf = jt & 1;
        if (jt + 1 < 32) {
            int j0n = (jbase + jt + 1) * 64;
            for (int t = tid; t < 512; t += 256) {
                int r = t >> 4, s4 = (t & 15) * 4;
                cpa16(smem_u32(&qjh[(buf ^ 1) * 2304 + r * QS + s4]), qhb + (size_t)r * NP + j0n + s4);
                cpa16(smem_u32(&qjl[(buf ^ 1) * 2304 + r * QS + s4]), qlb + (size_t)r * NP + j0n + s4);
            }
            cpa_commit();
        }
        const float* jhp = qjh + buf * 2304;
        const float* jlp = qjl + buf * 2304;

        float acc[2][2][4];
        #pragma unroll
        for (int a = 0; a < 2; a++)
            #pragma unroll
            for (int c = 0; c < 2; c++)
                #pragma unroll
                for (int e = 0; e < 4; e++) acc[a][c][e] = 0.f;

        #pragma unroll
        for (int ks = 0; ks < 4; ks++) {
            int k = ks * 8 + lc;
            uint32_t ah[2][4], al[2][4];
            #pragma unroll
            for (int mt = 0; mt < 2; mt++) {
                int ib = wi * 32 + mt * 16 + lr;
                ah[mt][0] = __float_as_uint(qih[k * QS + ib]);
                ah[mt][1] = __float_as_uint(qih[k * QS + ib + 8]);
                ah[mt][2] = __float_as_uint(qih[(k + 4) * QS + ib]);
                ah[mt][3] = __float_as_uint(qih[(k + 4) * QS + ib + 8]);
                al[mt][0] = __float_as_uint(qil[k * QS + ib]);
                al[mt][1] = __float_as_uint(qil[k * QS + ib + 8]);
                al[mt][2] = __float_as_uint(qil[(k + 4) * QS + ib]);
                al[mt][3] = __float_as_uint(qil[(k + 4) * QS + ib + 8]);
            }
            uint32_t bh[2][2], bl[2][2];
            #pragma unroll
            for (int nt = 0; nt < 2; nt++) {
                int jb = wj * 16 + nt * 8 + lr;
                bh[nt][0] = __float_as_uint(jhp[k * QS + jb]);
                bh[nt][1] = __float_as_uint(jhp[(k + 4) * QS + jb]);
                bl[nt][0] = __float_as_uint(jlp[k * QS + jb]);
                bl[nt][1] = __float_as_uint(jlp[(k + 4) * QS + jb]);
            }
            #pragma unroll
            for (int mt = 0; mt < 2; mt++)
                #pragma unroll
                for (int nt = 0; nt < 2; nt++) {
                    mma_tf32(acc[mt][nt], ah[mt], bh[nt]);
                    mma_tf32(acc[mt][nt], ah[mt], bl[nt]);
                    mma_tf32(acc[mt][nt], al[mt], bh[nt]);
                }
        }
        #pragma unroll
        for (int mt = 0; mt < 2; mt++) {
            #pragma unroll
            for (int half = 0; half < 2; half++) {
                int idx = mt * 2 + half;
                float v0 = acc[mt][0][half * 2], v1 = acc[mt][0][half * 2 + 1];
                float v2 = acc[mt][1][half * 2], v3 = acc[mt][1][half * 2 + 1];
                float tmax = fmaxf(fmaxf(v0, v1), fmaxf(v2, v3));
                float mnew = fmaxf(m_t[idx], tmax);
                float sc = __expf(m_t[idx] - mnew);
                float add = __expf(v0 - mnew) + __expf(v1 - mnew)
                          + __expf(v2 - mnew) + __expf(v3 - mnew);
                s_t[idx] = s_t[idx] * sc + add;
                m_t[idx] = mnew;
            }
        }
    }
    #pragma unroll
    for (int mt = 0; mt < 2; mt++)
        #pragma unroll
        for (int half = 0; half < 2; half++) {
            int row = wi * 32 + mt * 16 + half * 8 + lr;
            int slot = wj * 4 + lc;
            red_m[row * 16 + slot] = m_t[mt * 2 + half];
            red_s[row * 16 + slot] = s_t[mt * 2 + half];
        }
    __syncthreads();
    if (tid < 64) {
        float mt_ = -1e30f;
        #pragma unroll
        for (int k = 0; k < 16; k++) mt_ = fmaxf(mt_, red_m[tid * 16 + k]);
        float s = 0.f;
        #pragma unroll
        for (int k = 0; k < 16; k++)
            s += red_s[tid * 16 + k] * __expf(red_m[tid * 16 + k] - mt_);
        size_t p = ((size_t)jh * BB + b) * NP + i0 + tid;
        rowm_p[p] = mt_;
        rows_p[p] = s;
    }
}

__global__ void stats_merge_k(const float* __restrict__ mp, const float* __restrict__ sp,
                              float* __restrict__ rowm, float* __restrict__ rowsinv)
{
    int i = blockIdx.x * 256 + threadIdx.x;
    float m0 = mp[i], m1 = mp[BB * NP + i];
    float s0 = sp[i], s1 = sp[BB * NP + i];
    float m = fmaxf(m0, m1);
    float s = s0 * __expf(m0 - m) + s1 * __expf(m1 - m);
    rowm[i] = m;
    rowsinv[i] = 1.f / s;
}

// =====================================================================
// PASS 2: fused energy->softmax->colsum->v@attn->residual.
// =====================================================================
#define FUSE_SMEM_FLOATS 37952
__global__ __launch_bounds__(256) void attn_fuse_k(
    const float* __restrict__ qhi, const float* __restrict__ qlo,
    const float* __restrict__ v,
    const float* __restrict__ rowm, const float* __restrict__ rowsinv,
    const float* __restrict__ hin, size_t sHin,
    float* __restrict__ u)
{
    extern __shared__ __align__(16) float sm[];
    float* qjh = sm;                  // 2304
    float* qjl = sm + 2304;           // 2304
    float* qih = sm + 4608;           // [2][2304]
    float* qil = sm + 9216;           // [2][2304]
    float* v_s = sm + 13824;          // [2][9728]
    float* at_s = sm + 33280;         // [64][72]
    float* cs_s = sm + 37888;         // 64

    const int b = blockIdx.y;
    const int n0 = blockIdx.x * 64;
    const float* qhb = qhi + (size_t)b * 32 * NP;
    const float* qlb = qlo + (size_t)b * 32 * NP;
    const float* vb = v + (size_t)b * 128 * NP;
    const int tid = threadIdx.x;
    const int wid = tid >> 5, lane = tid & 31;
    const int lr = lane >> 2, lc = lane & 3;
    const int w1 = wid >> 1;
    const int w2 = wid & 1;

    if (tid < 64) cs_s[tid] = 0.f;

    for (int t = tid; t < 512; t += 256) {
        int r = t >> 4, s4 = (t & 15) * 4;
        cpa16(smem_u32(qjh + r * 72 + s4), qhb + (size_t)r * NP + n0 + s4);
        cpa16(smem_u32(qjl + r * 72 + s4), qlb + (size_t)r * NP + n0 + s4);
        cpa16(smem_u32(qih + r * 72 + s4), qhb + (size_t)r * NP + s4);
        cpa16(smem_u32(qil + r * 72 + s4), qlb + (size_t)r * NP + s4);
    }
    for (int t = tid; t < 2048; t += 256) {
        int r = t >> 4, s4 = (t & 15) * 4;
        cpa16(smem_u32(v_s + r * 76 + s4), vb + (size_t)r * NP + s4);
    }
    cpa_commit();

    float acc_v[2][4][4];
    #pragma unroll
    for (int a = 0; a < 2; a++)
        #pragma unroll
        for (int c = 0; c < 4; c++)
            #pragma unroll
            for (int e = 0; e < 4; e++) acc_v[a][c][e] = 0.f;
    float cs_part[8];
    #pragma unroll
    for (int p = 0; p < 8; p++) cs_part[p] = 0.f;

    for (int it = 0; it < 64; it++) {
        cpa_wait0(); __syncthreads();
        int buf = it & 1;
        if (it + 1 < 64) {
            int i0n = (it + 1) * 64;
            for (int t = tid; t < 512; t += 256) {
                int r = t >> 4, s4 = (t & 15) * 4;
                cpa16(smem_u32(qih + (buf ^ 1) * 2304 + r * 72 + s4), qhb + (size_t)r * NP + i0n + s4);
                cpa16(smem_u32(qil + (buf ^ 1) * 2304 + r * 72 + s4), qlb + (size_t)r * NP + i0n + s4);
            }
            for (int t = tid; t < 2048; t += 256) {
                int r = t >> 4, s4 = (t & 15) * 4;
                cpa16(smem_u32(v_s + (buf ^ 1) * 9728 + r * 76 + s4), vb + (size_t)r * NP + i0n + s4);
            }
            cpa_commit();
        }
        const int i0 = it * 64;
        const float* qiph = qih + buf * 2304;
        const float* qipl = qil + buf * 2304;
        const float* vp   = v_s + buf * 9728;

        float ae[4][4];
        #pragma unroll
        for (int c = 0; c < 4; c++)
            #pragma unroll
            for (int e = 0; e < 4; e++) ae[c][e] = 0.f;
        #pragma unroll
        for (int ks = 0; ks < 4; ks++) {
            int k = ks * 8 + lc;
            int ib = w1 * 16 + lr;
            uint32_t ah[4], al[4];
            ah[0] = __float_as_uint(qiph[k * 72 + ib]);
            ah[1] = __float_as_uint(qiph[k * 72 + ib + 8]);
            ah[2] = __float_as_uint(qiph[(k + 4) * 72 + ib]);
            ah[3] = __float_as_uint(qiph[(k + 4) * 72 + ib + 8]);
            al[0] = __float_as_uint(qipl[k * 72 + ib]);
            al[1] = __float_as_uint(qipl[k * 72 + ib + 8]);
            al[2] = __float_as_uint(qipl[(k + 4) * 72 + ib]);
            al[3] = __float_as_uint(qipl[(k + 4) * 72 + ib + 8]);
            #pragma unroll
            for (int nt = 0; nt < 4; nt++) {
                int jb = w2 * 32 + nt * 8 + lr;
                uint32_t bh[2], bl[2];
                bh[0] = __float_as_uint(qjh[k * 72 + jb]);
                bh[1] = __float_as_uint(qjh[(k + 4) * 72 + jb]);
                bl[0] = __float_as_uint(qjl[k * 72 + jb]);
                bl[1] = __float_as_uint(qjl[(k + 4) * 72 + jb]);
                mma_tf32(ae[nt], ah, bh);
                mma_tf32(ae[nt], ah, bl);
                mma_tf32(ae[nt], al, bh);
            }
        }
        {
            int gi = b * NP + i0 + w1 * 16 + lr;
            float m0 = rowm[gi],     m1 = rowm[gi + 8];
            float si0 = rowsinv[gi], si1 = rowsinv[gi + 8];
            #pragma unroll
            for (int nt = 0; nt < 4; nt++) {
                float e00 = __expf(ae[nt][0] - m0) * si0;
                float e01 = __expf(ae[nt][1] - m0) * si0;
                float e10 = __expf(ae[nt][2] - m1) * si1;
                float e11 = __expf(ae[nt][3] - m1) * si1;
                int jb = w2 * 32 + nt * 8 + lc * 2;
                int ib = w1 * 16 + lr;
                *(float2*)&at_s[ib * 72 + jb] =
                    make_float2(__uint_as_float(f2tf(e00)), __uint_as_float(f2tf(e01)));
                *(float2*)&at_s[(ib + 8) * 72 + jb] =
                    make_float2(__uint_as_float(f2tf(e10)), __uint_as_float(f2tf(e11)));
                cs_part[nt * 2]     += e00 + e10;
                cs_part[nt * 2 + 1] += e01 + e11;
            }
        }
        __syncthreads();

        #pragma unroll
        for (int ks = 0; ks < 8; ks++) {
            int k = ks * 8 + lc;
            uint32_t av[2][4];
            #pragma unroll
            for (int mt = 0; mt < 2; mt++) {
                int cb = w1 * 32 + mt * 16 + lr;
                av[mt][0] = __float_as_uint(vp[cb * 76 + k]);
                av[mt][1] = __float_as_uint(vp[(cb + 8) * 76 + k]);
                av[mt][2] = __float_as_uint(vp[cb * 76 + k + 4]);
                av[mt][3] = __float_as_uint(vp[(cb + 8) * 76 + k + 4]);
            }
            #pragma unroll
            for (int nt = 0; nt < 4; nt++) {
                int jb = w2 * 32 + nt * 8 + lr;
                uint32_t bv[2];
                bv[0] = __float_as_uint(at_s[k * 72 + jb]);
                bv[1] = __float_as_uint(at_s[(k + 4) * 72 + jb]);
                #pragma unroll
                for (int mt = 0; mt < 2; mt++)
                    mma_tf32(acc_v[mt][nt], av[mt], bv);
            }
        }
    }

    #pragma unroll
    for (int p = 0; p < 8; p++) {
        int jb = w2 * 32 + (p >> 1) * 8 + lc * 2 + (p & 1);
        atomicAdd(&cs_s[jb], cs_part[p]);
    }
    __syncthreads();
    if (tid < 64) cs_s[tid] = 1.f / (1e-9f + cs_s[tid]);
    __syncthreads();

    #pragma unroll
    for (int mt = 0; mt < 2; mt++) {
        #pragma unroll
        for (int half = 0; half < 2; half++) {
            int c = w1 * 32 + mt * 16 + half * 8 + lr;
            #pragma unroll
            for (int nt = 0; nt < 4; nt++) {
                int jb = w2 * 32 + nt * 8 + lc * 2;
                float ci0 = cs_s[jb], ci1 = cs_s[jb + 1];
                float2 hv = *(const float2*)&hin[(size_t)b * sHin + (size_t)c * NP + n0 + jb];
                float2 o;
                o.x = hv.x - acc_v[mt][nt][half * 2]     * ci0;
                o.y = hv.y - acc_v[mt][nt][half * 2 + 1] * ci1;
                *(float2*)&u[(size_t)b * 128 * NP + (size_t)c * NP + n0 + jb] = o;
            }
        }
    }
}

// ---------------- tf32 tensor-core GEMM with fused epilogues ----------------
template<int BN>
__device__ __forceinline__ void t_load(float* As, float* Bs,
    const float* __restrict__ Ab, const float* __restrict__ Bb,
    int tid, int kt, int lda, int N)
{
    constexpr int ASTR = 20;
    constexpr int BSTR = BN + 8;
    #pragma unroll
    for (int i = 0; i < 2; i++) {
        int idx = tid + i * 256;
        int row = idx >> 2, seg = (idx & 3) * 4;
        cpa16(smem_u32(As + row * ASTR + seg), Ab + (size_t)row * lda + kt * 16 + seg);
    }
    constexpr int BF4 = BN / 64;
    #pragma unroll
    for (int i = 0; i < BF4; i++) {
        int idx = tid + i * 256;
        int row = idx / (BN / 4), seg = (idx % (BN / 4)) * 4;
        cpa16(smem_u32(Bs + row * BSTR + seg), Bb + (size_t)(kt * 16 + row) * N + seg);
    }
}

// OUT: 0 = fp32 store, 2 = tf32-rounded store
template<int BN, int ACT, int RES, int OUT>
__global__ __launch_bounds__(256) void tgemm_k(int M, int N, int K, int lda,
    const float* __restrict__ A, size_t sA,
    const float* __restrict__ B, size_t sB,
    float* __restrict__ C, size_t sC,
    const float* __restrict__ rb, size_t sRB,
    const float* __restrict__ bng, const float* __restrict__ bnb, float bninv,
    const float* __restrict__ res, size_t sRes,
    float slope)
{
    constexpr int BM = 128, BK = 16;
    constexpr int ASTR = 20;
    constexpr int BSTR = BN + 8;
    constexpr int WN = BN / 4;
    constexpr int NT = WN / 8;
    __shared__ __align__(16) float As[2][BM * ASTR];
    __shared__ __align__(16) float Bs[2][BK * BSTR];

    const int b = blockIdx.z;
    const int m0 = blockIdx.y * BM, n0 = blockIdx.x * BN;
    const float* Ab = A + (size_t)b * sA + (size_t)m0 * lda;
    const float* Bb = B + (size_t)b * sB + n0;
    const int tid = threadIdx.x;
    const int wid = tid >> 5, lane = tid & 31;
    const int wm = wid >> 2, wn = wid & 3;
    const int lr = lane >> 2, lc = lane & 3;

    float acc[4][NT][4];
    #pragma unroll
    for (int i = 0; i < 4; i++)
        #pragma unroll
        for (int j = 0; j < NT; j++)
            #pragma unroll
            for (int e = 0; e < 4; e++) acc[i][j][e] = 0.f;

    const int nk = K / BK;
    t_load<BN>(As[0], Bs[0], Ab, Bb, tid, 0, lda, N);
    cpa_commit();

    for (int kt = 0; kt < nk; kt++) {
        cpa_wait0();
        __syncthreads();
        int buf = kt & 1;
        if (kt + 1 < nk) {
            t_load<BN>(As[buf ^ 1], Bs[buf ^ 1], Ab, Bb, tid, kt + 1, lda, N);
            cpa_commit();
        }
        #pragma unroll
        for (int ks = 0; ks < 2; ks++) {
            const float* Ap = &As[buf][0];
            const float* Bp = &Bs[buf][0];
            uint32_t af[4][4];
            #pragma unroll
            for (int mt = 0; mt < 4; mt++) {
                int r = wm * 64 + mt * 16 + lr;
                int c = ks * 8 + lc;
                af[mt][0] = f2tf(Ap[(r    ) * ASTR + c    ]);
                af[mt][1] = f2tf(Ap[(r + 8) * ASTR + c    ]);
                af[mt][2] = f2tf(Ap[(r    ) * ASTR + c + 4]);
                af[mt][3] = f2tf(Ap[(r + 8) * ASTR + c + 4]);
            }
            uint32_t bf[NT][2];
            #pragma unroll
            for (int nt = 0; nt < NT; nt++) {
                int cgl = wn * WN + nt * 8 + lr;
                int k = ks * 8 + lc;
                bf[nt][0] = f2tf(Bp[(k    ) * BSTR + cgl]);
                bf[nt][1] = f2tf(Bp[(k + 4) * BSTR + cgl]);
            }
            #pragma unroll
            for (int mt = 0; mt < 4; mt++)
                #pragma unroll
                for (int nt = 0; nt < NT; nt++)
                    mma_tf32(acc[mt][nt], af[mt], bf[nt]);
        }
        __syncthreads();
    }

    #pragma unroll
    for (int mt = 0; mt < 4; mt++) {
        #pragma unroll
        for (int h = 0; h < 2; h++) {
            int mm = m0 + wm * 64 + mt * 16 + h * 8 + lr;
            float scale = (bng ? bng[mm] : 1.f) * bninv;
            float shift = bnb ? bnb[mm] : 0.f;
            float rbv   = rb  ? rb[(size_t)b * sRB + mm] : 0.f;
            #pragma unroll
            for (int nt = 0; nt < NT; nt++) {
                int n = n0 + wn * WN + nt * 8 + lc * 2;
                float v0 = acc[mt][nt][h * 2 + 0];
                float v1 = acc[mt][nt][h * 2 + 1];
                v0 = (v0 + rbv) * scale + shift;
                v1 = (v1 + rbv) * scale + shift;
                if (ACT == 1) { v0 = fmaxf(v0, 0.f); v1 = fmaxf(v1, 0.f); }
                else if (ACT == 2) { v0 = v0 > 0.f ? v0 : slope * v0; v1 = v1 > 0.f ? v1 : slope * v1; }
                if (RES == 1) {
                    v0 = res[(size_t)b * sRes + (size_t)mm * N + n] + v0;
                    v1 = res[(size_t)b * sRes + (size_t)mm * N + n + 1] + v1;
                } else if (RES == 2) {
                    v0 = res[(size_t)b * sRes + (size_t)mm * N + n] - v0;
                    v1 = res[(size_t)b * sRes + (size_t)mm * N + n + 1] - v1;
                }
                if (OUT == 2) {
                    v0 = __uint_as_float(f2tf(v0));
                    v1 = __uint_as_float(f2tf(v1));
                }
                *(float2*)&C[(size_t)b * sC + (size_t)mm * N + n] = make_float2(v0, v1);
            }
        }
    }
}

// ---------------- fp32 tiled SGEMM (q only) ----------------
// OMODE: 1 = write tf32 hi to C and lo to C2
template<int OMODE>
__global__ void gemm_k(int M, int N, int K, int lda,
    const float* __restrict__ A, size_t sA,
    const float* __restrict__ B, size_t sB,
    float* __restrict__ C, float* __restrict__ C2, size_t sC)
{
    __shared__ float As[16][68];
    __shared__ float Bs[16][68];
    const int b  = blockIdx.z;
    const float* Ab = A + (size_t)b * sA;
    const float* Bb = B + (size_t)b * sB;
    const int m0 = blockIdx.y * 64;
    const int n0 = blockIdx.x * 64;
    const int tid = threadIdx.x;
    const int tx = tid & 15, ty = tid >> 4;

    float acc[4][4];
    #pragma unroll
    for (int i = 0; i < 4; i++)
        #pragma unroll
        for (int j = 0; j < 4; j++) acc[i][j] = 0.f;

    for (int k0 = 0; k0 < K; k0 += 16) {
        {
            int m = tid >> 2, kq = tid & 3;
            float4 av = make_float4(0.f, 0.f, 0.f, 0.f);
            if (m0 + m < M)
                av = *(const float4*)&Ab[(size_t)(m0 + m) * lda + k0 + kq * 4];
            As[kq * 4 + 0][m] = av.x;
            As[kq * 4 + 1][m] = av.y;
            As[kq * 4 + 2][m] = av.z;
            As[kq * 4 + 3][m] = av.w;
        }
        {
            int kk = tid >> 4, nq = tid & 15;
            float4 bv = *(const float4*)&Bb[(size_t)(k0 + kk) * N + n0 + nq * 4];
            *(float4*)&Bs[kk][nq * 4] = bv;
        }
        __syncthreads();
        #pragma unroll
        for (int k = 0; k < 16; k++) {
            float4 a4 = *(float4*)&As[k][ty * 4];
            float4 b4 = *(float4*)&Bs[k][tx * 4];
            float ar[4] = {a4.x, a4.y, a4.z, a4.w};
            float br[4] = {b4.x, b4.y, b4.z, b4.w};
            #pragma unroll
            for (int i = 0; i < 4; i++)
                #pragma unroll
                for (int j = 0; j < 4; j++)
                    acc[i][j] = fmaf(ar[i], br[j], acc[i][j]);
        }
        __syncthreads();
    }

    #pragma unroll
    for (int i = 0; i < 4; i++) {
        int m = m0 + ty * 4 + i;
        if (m >= M) continue;
        #pragma unroll
        for (int j = 0; j < 4; j++) {
            int n = n0 + tx * 4 + j;
            float v = acc[i][j];
            size_t off = (size_t)b * sC + (size_t)m * N + n;
            if (OMODE == 1) {
                uint32_t hi, lo; split_tf(v, hi, lo);
                C[off]  = __uint_as_float(hi);
                C2[off] = __uint_as_float(lo);
            } else {
                C[off] = v;
            }
        }
    }
}

// ---------------- conv1 ----------------
__global__ void conv1_k(const float* __restrict__ x, const float* __restrict__ w1,
                        const float* __restrict__ g, const float* __restrict__ bb,
                        float inv, float* __restrict__ out)
{
    int idx = blockIdx.x * blockDim.x + threadIdx.x;
    int n = idx & (NP - 1);
    int o = (idx / NP) & 127;
    int b = idx / (128 * NP);
    const float* xp = x + ((size_t)b * 15 + 9) * NP + n;
    float s = w1[o * 3 + 0] * xp[0] + w1[o * 3 + 1] * xp[NP] + w1[o * 3 + 2] * xp[2 * NP];
    s = s * g[o] * inv + bb[o];
    out[idx] = fmaxf(s, 0.f);
}

// ---------------- global max/mean pooling over N ----------------
__global__ void pool_k(const float* __restrict__ hf, float* __restrict__ xmax, float* __restrict__ xavg)
{
    int bc = blockIdx.x;
    const float* p = hf + (size_t)bc * NP;
    int t = threadIdx.x;
    float mx = -1e30f, sm = 0.f;
    for (int i = t; i < NP; i += 256) { float v = p[i]; mx = fmaxf(mx, v); sm += v; }
    __shared__ float rm[256], rs[256];
    rm[t] = mx; rs[t] = sm; __syncthreads();
    for (int s = 128; s > 0; s >>= 1) {
        if (t < s) { rm[t] = fmaxf(rm[t], rm[t + s]); rs[t] += rs[t + s]; }
        __syncthreads();
    }
    if (t == 0) { xmax[bc] = rm[0]; xavg[bc] = rs[0] * (1.f / NP); }
}

// ---------------- fold pooled channels of ws1 into per-row bias ----------------
__global__ void r1_k(const float* __restrict__ ws1, const float* __restrict__ bs1,
                     const float* __restrict__ xmax, const float* __restrict__ xavg,
                     float* __restrict__ r1)
{
    int idx = blockIdx.x * blockDim.x + threadIdx.x;
    if (idx >= BB * 512) return;
    int b = idx / 512, o = idx % 512;
    const float* w = ws1 + (size_t)o * 3072;
    float s = bs1[o];
    #pragma unroll 4
    for (int c = 0; c < 1024; c++)
        s += w[1024 + c] * xmax[b * 1024 + c] + w[2048 + c] * xavg[b * 1024 + c];
    r1[idx] = s;
}

// ---------------- ws3 (8x256) + log_softmax + transpose ----------------
__global__ void final_k(const float* __restrict__ s2, const float* __restrict__ ws3,
                        const float* __restrict__ bs3, float* __restrict__ out)
{
    __shared__ float w[8 * 256];
    __shared__ float bias[8];
    int t = threadIdx.x;
    for (int i = t; i < 2048; i += blockDim.x) w[i] = ws3[i];
    if (t < 8) bias[t] = bs3[t];
    __syncthreads();
    int idx = blockIdx.x * blockDim.x + t;
    int b = idx / NP, n = idx & (NP - 1);
    const float* sp = s2 + (size_t)b * 256 * NP + n;
    float l[8];
    #pragma unroll
    for (int k = 0; k < 8; k++) l[k] = bias[k];
    for (int c = 0; c < 256; c++) {
        float v = sp[(size_t)c * NP];
        #pragma unroll
        for (int k = 0; k < 8; k++) l[k] = fmaf(w[k * 256 + c], v, l[k]);
    }
    float m = l[0];
    #pragma unroll
    for (int k = 1; k < 8; k++) m = fmaxf(m, l[k]);
    float s = 0.f;
    #pragma unroll
    for (int k = 0; k < 8; k++) s += expf(l[k] - m);
    float lse = m + logf(s);
    #pragma unroll
    for (int k = 0; k < 8; k++)
        out[((size_t)b * NP + n) * 8 + k] = l[k] - lse;
}

// ---------------- host launch ----------------
extern "C" void kernel_launch(void* const* d_in, const int* in_sizes, int n_in,
                              void* d_out, int out_size)
{
    const float* x      = (const float*)d_in[0];
    const float* w1     = (const float*)d_in[1];
    const float* bn1_g  = (const float*)d_in[2];
    const float* bn1_b  = (const float*)d_in[3];
    const float* w2     = (const float*)d_in[4];
    const float* bn2_g  = (const float*)d_in[5];
    const float* bn2_b  = (const float*)d_in[6];
    const float* sa_wqk = (const float*)d_in[7];
    const float* sa_wv  = (const float*)d_in[8];
    const float* sa_bv  = (const float*)d_in[9];
    const float* sa_wt  = (const float*)d_in[10];
    const float* sa_bt  = (const float*)d_in[11];
    const float* sa_bng = (const float*)d_in[12];
    const float* sa_bnb = (const float*)d_in[13];
    const float* wf     = (const float*)d_in[14];
    const float* bnf_g  = (const float*)d_in[15];
    const float* bnf_b  = (const float*)d_in[16];
    const float* ws1    = (const float*)d_in[17];
    const float* bs1    = (const float*)d_in[18];
    const float* bns1_g = (const float*)d_in[19];
    const float* bns1_b = (const float*)d_in[20];
    const float* ws2    = (const float*)d_in[21];
    const float* bs2    = (const float*)d_in[22];
    const float* bns2_g = (const float*)d_in[23];
    const float* bns2_b = (const float*)d_in[24];
    const float* ws3    = (const float*)d_in[25];
    const float* bs3    = (const float*)d_in[26];
    float* out = (float*)d_out;

    float *c1, *h0, *qhi, *qlo, *v, *u, *rowm, *rowsinv, *rowm_p, *rows_p;
    float *feats, *hf, *xmax, *xavg, *r1, *s1, *s2;
    cudaGetSymbolAddress((void**)&c1,      g_c1);
    cudaGetSymbolAddress((void**)&h0,      g_h0);
    cudaGetSymbolAddress((void**)&qhi,     g_qhi);
    cudaGetSymbolAddress((void**)&qlo,     g_qlo);
    cudaGetSymbolAddress((void**)&v,       g_v);
    cudaGetSymbolAddress((void**)&u,       g_u);
    cudaGetSymbolAddress((void**)&rowm,    g_rowm);
    cudaGetSymbolAddress((void**)&rowsinv, g_rowsinv);
    cudaGetSymbolAddress((void**)&rowm_p,  g_rowm_p);
    cudaGetSymbolAddress((void**)&rows_p,  g_rows_p);
    cudaGetSymbolAddress((void**)&feats,   g_feats);
    cudaGetSymbolAddress((void**)&hf,      g_hf);
    cudaGetSymbolAddress((void**)&xmax,    g_xmax);
    cudaGetSymbolAddress((void**)&xavg,    g_xavg);
    cudaGetSymbolAddress((void**)&r1,      g_r1);
    cudaGetSymbolAddress((void**)&s1,      g_s1);
    cudaGetSymbolAddress((void**)&s2,      g_s2);

    const float INV = 0.999995000037499219f;   // 1/sqrt(1 + 1e-5)
    dim3 blk(256);
    const int STATS_SMEM = STATS_SMEM_FLOATS * 4;
    const int FUSE_SMEM  = FUSE_SMEM_FLOATS * 4;
    cudaFuncSetAttribute(attn_stats_k, cudaFuncAttributeMaxDynamicSharedMemorySize, STATS_SMEM);
    cudaFuncSetAttribute(attn_fuse_k,  cudaFuncAttributeMaxDynamicSharedMemorySize, FUSE_SMEM);

    // conv1: 3 -> 128, bn+relu
    conv1_k<<<(BB * 128 * NP) / 256, blk>>>(x, w1, bn1_g, bn1_b, INV, c1);

    // conv2: 128 -> 128, bn+relu  [tf32 tensor]
    tgemm_k<64,1,0,0><<<dim3(NP/64, 1, BB), blk>>>(128, NP, 128, 128,
        w2, 0, c1, (size_t)128*NP, h0, (size_t)128*NP,
        nullptr, 0, bn2_g, bn2_b, INV, nullptr, 0, 0.f);

    for (int i = 0; i < 4; i++) {
        const float* hin = (i == 0) ? h0 : feats + (size_t)(i - 1) * 128 * NP;
        size_t sHin = (i == 0) ? (size_t)128 * NP : (size_t)512 * NP;

        // q = wqk @ h  (32 x 4096) fp32 -> pre-split tf32 hi/lo
        gemm_k<1><<<dim3(NP/64, 1, BB), blk>>>(32, NP, 128, 128,
            sa_wqk + (size_t)i*32*128, 0, hin, sHin, qhi, qlo, (size_t)32*NP);

        // pass 1: row softmax stats (2 j-halves) + merge
        attn_stats_k<<<dim3(NP/64, BB, 2), blk, STATS_SMEM>>>(qhi, qlo, rowm_p, rows_p);
        stats_merge_k<<<(BB * NP) / 256, blk>>>(rowm_p, rows_p, rowm, rowsinv);

        // v = wv @ h + bv, tf32-rounded out  [tf32 tensor]
        tgemm_k<64,0,0,2><<<dim3(NP/64, 1, BB), blk>>>(128, NP, 128, 128,
            sa_wv + (size_t)i*128*128, 0, hin, sHin, v, (size_t)128*NP,
            sa_bv + (size_t)i*128, 0, nullptr, nullptr, 1.f, nullptr, 0, 0.f);

        // pass 2: fused energy->softmax->colsum->v@attn->residual: u = h - x_r
        attn_fuse_k<<<dim3(NP/64, BB), blk, FUSE_SMEM>>>(qhi, qlo, v, rowm, rowsinv, hin, sHin, u);

        // h_new = h + relu(bn(wt @ u + bt))  [tf32 tensor]
        tgemm_k<64,1,1,0><<<dim3(NP/64, 1, BB), blk>>>(128, NP, 128, 128,
            sa_wt + (size_t)i*128*128, 0, u, (size_t)128*NP,
            feats + (size_t)i*128*NP, (size_t)512*NP,
            sa_bt + (size_t)i*128, 0, sa_bng + (size_t)i*128, sa_bnb + (size_t)i*128, INV,
            hin, sHin, 0.f);
    }

    // wf: 512 -> 1024, bn + leaky_relu(0.2)  [tf32 tensor]
    tgemm_k<128,2,0,0><<<dim3(NP/128, 1024/128, BB), blk>>>(1024, NP, 512, 512,
        wf, 0, feats, (size_t)512*NP, hf, (size_t)1024*NP,
        nullptr, 0, bnf_g, bnf_b, INV, nullptr, 0, 0.2f);

    pool_k<<<BB * 1024, blk>>>(hf, xmax, xavg);
    r1_k<<<(BB * 512 + 255) / 256, blk>>>(ws1, bs1, xmax, xavg, r1);

    // ws1 (first 1024 input channels of 3072; pooled part folded into r1)  [tf32]
    tgemm_k<128,1,0,0><<<dim3(NP/128, 512/128, BB), blk>>>(512, NP, 1024, 3072,
        ws1, 0, hf, (size_t)1024*NP, s1, (size_t)512*NP,
        r1, 512, bns1_g, bns1_b, INV, nullptr, 0, 0.f);

    // ws2: 512 -> 256, bn + relu  [tf32]
    tgemm_k<128,1,0,0><<<dim3(NP/128, 256/128, BB), blk>>>(256, NP, 512, 512,
        ws2, 0, s1, (size_t)512*NP, s2, (size_t)256*NP,
        bs2, 0, bns2_g, bns2_b, INV, nullptr, 0, 0.f);

    // ws3 + log_softmax + transpose
    final_k<<<(BB * NP) / 256, blk>>>(s2, ws3, bs3, out);
}

// round 10
// speedup vs baseline: 2.8961x; 1.0760x over previous
#include <cuda_runtime.h>
#include <cstdint>

#define NP 4096
#define BB 2

// ---------------- scratch (static device globals; no allocation) ----------------
__device__ float g_c1[BB*128*NP];
__device__ float g_h0[BB*128*NP];
__device__ float g_qhi[BB*32*NP];
__device__ float g_qlo[BB*32*NP];
__device__ float g_v [BB*128*NP];
__device__ float g_u [BB*128*NP];
__device__ float g_rowm[BB*NP];
__device__ float g_rowsinv[BB*NP];
__device__ float g_rowm_p[4*BB*NP];
__device__ float g_rows_p[4*BB*NP];
__device__ float g_pacc[(size_t)2*BB*128*NP];   // partial x_r (8 MB)
__device__ float g_pcs[2*BB*NP];                // partial colsum
__device__ float g_feats[BB*512*NP];
__device__ float g_hf[BB*1024*NP];
__device__ float g_xmax[BB*1024];
__device__ float g_xavg[BB*1024];
__device__ float g_r1[BB*512];
__device__ float g_s1[BB*512*NP];
__device__ float g_s2[BB*256*NP];

// ---------------- PTX helpers ----------------
__device__ __forceinline__ uint32_t smem_u32(const void* p) {
    return (uint32_t)__cvta_generic_to_shared(p);
}
__device__ __forceinline__ void cpa16(uint32_t s, const void* g) {
    asm volatile("cp.async.cg.shared.global [%0], [%1], 16;" :: "r"(s), "l"(g));
}
__device__ __forceinline__ void cpa_commit() { asm volatile("cp.async.commit_group;"); }
__device__ __forceinline__ void cpa_wait0()  { asm volatile("cp.async.wait_group 0;"); }
__device__ __forceinline__ uint32_t f2tf(float f) {
    uint32_t r;
    asm("cvt.rna.tf32.f32 %0, %1;" : "=r"(r) : "f"(f));
    return r;
}
__device__ __forceinline__ void split_tf(float x, uint32_t& hi, uint32_t& lo) {
    hi = f2tf(x);
    lo = f2tf(x - __uint_as_float(hi));
}
__device__ __forceinline__ void mma_tf32(float* c, const uint32_t* a, const uint32_t* b) {
    asm volatile(
        "mma.sync.aligned.m16n8k8.row.col.f32.tf32.tf32.f32 "
        "{%0,%1,%2,%3}, {%4,%5,%6,%7}, {%8,%9}, {%0,%1,%2,%3};"
        : "+f"(c[0]), "+f"(c[1]), "+f"(c[2]), "+f"(c[3])
        : "r"(a[0]), "r"(a[1]), "r"(a[2]), "r"(a[3]), "r"(b[0]), "r"(b[1]));
}

// =====================================================================
// PASS 1: flash row stats over a QUARTER of the j-range per block.
// =====================================================================
#define STATS_SMEM_FLOATS 15872
__global__ __launch_bounds__(256) void attn_stats_k(
    const float* __restrict__ qhi, const float* __restrict__ qlo,
    float* __restrict__ rowm_p, float* __restrict__ rows_p)
{
    constexpr int QS = 72;
    extern __shared__ __align__(16) float sm[];
    float* qih = sm;                 // 2304
    float* qil = sm + 2304;          // 2304
    float* qjh = sm + 4608;          // [2][2304]
    float* qjl = sm + 9216;          // [2][2304]
    float* red_m = sm + 13824;       // 1024
    float* red_s = sm + 14848;       // 1024

    const int b = blockIdx.y;
    const int i0 = blockIdx.x * 64;
    const int jh = blockIdx.z;       // 0..3 j-quarter
    const float* qhb = qhi + (size_t)b * 32 * NP;
    const float* qlb = qlo + (size_t)b * 32 * NP;
    const int tid = threadIdx.x;
    const int wid = tid >> 5, lane = tid & 31;
    const int lr = lane >> 2, lc = lane & 3;
    const int wi = wid >> 2;
    const int wj = wid & 3;

    for (int t = tid; t < 512; t += 256) {
        int r = t >> 4, s4 = (t & 15) * 4;
        *(float4*)&qih[r * QS + s4] = *(const float4*)&qhb[(size_t)r * NP + i0 + s4];
        *(float4*)&qil[r * QS + s4] = *(const float4*)&qlb[(size_t)r * NP + i0 + s4];
    }
    const int jbase = jh * 16;       // tile index offset (16 tiles of 64)
    for (int t = tid; t < 512; t += 256) {
        int r = t >> 4, s4 = (t & 15) * 4;
        cpa16(smem_u32(&qjh[r * QS + s4]), qhb + (size_t)r * NP + jbase * 64 + s4);
        cpa16(smem_u32(&qjl[r * QS + s4]), qlb + (size_t)r * NP + jbase * 64 + s4);
    }
    cpa_commit();

    float m_t[4], s_t[4];
    #pragma unroll
    for (int k = 0; k < 4; k++) { m_t[k] = -1e30f; s_t[k] = 0.f; }

    for (int jt = 0; jt < 16; jt++) {
        cpa_wait0(); __syncthreads();
        int buf = jt & 1;
        if (jt + 1 < 16) {
            int j0n = (jbase + jt + 1) * 64;
            for (int t = tid; t < 512; t += 256) {
                int r = t >> 4, s4 = (t & 15) * 4;
                cpa16(smem_u32(&qjh[(buf ^ 1) * 2304 + r * QS + s4]), qhb + (size_t)r * NP + j0n + s4);
                cpa16(smem_u32(&qjl[(buf ^ 1) * 2304 + r * QS + s4]), qlb + (size_t)r * NP + j0n + s4);
            }
            cpa_commit();
        }
        const float* jhp = qjh + buf * 2304;
        const float* jlp = qjl + buf * 2304;

        float acc[2][2][4];
        #pragma unroll
        for (int a = 0; a < 2; a++)
            #pragma unroll
            for (int c = 0; c < 2; c++)
                #pragma unroll
                for (int e = 0; e < 4; e++) acc[a][c][e] = 0.f;

        #pragma unroll
        for (int ks = 0; ks < 4; ks++) {
            int k = ks * 8 + lc;
            uint32_t ah[2][4], al[2][4];
            #pragma unroll
            for (int mt = 0; mt < 2; mt++) {
                int ib = wi * 32 + mt * 16 + lr;
                ah[mt][0] = __float_as_uint(qih[k * QS + ib]);
                ah[mt][1] = __float_as_uint(qih[k * QS + ib + 8]);
                ah[mt][2] = __float_as_uint(qih[(k + 4) * QS + ib]);
                ah[mt][3] = __float_as_uint(qih[(k + 4) * QS + ib + 8]);
                al[mt][0] = __float_as_uint(qil[k * QS + ib]);
                al[mt][1] = __float_as_uint(qil[k * QS + ib + 8]);
                al[mt][2] = __float_as_uint(qil[(k + 4) * QS + ib]);
                al[mt][3] = __float_as_uint(qil[(k + 4) * QS + ib + 8]);
            }
            uint32_t bh[2][2], bl[2][2];
            #pragma unroll
            for (int nt = 0; nt < 2; nt++) {
                int jb = wj * 16 + nt * 8 + lr;
                bh[nt][0] = __float_as_uint(jhp[k * QS + jb]);
                bh[nt][1] = __float_as_uint(jhp[(k + 4) * QS + jb]);
                bl[nt][0] = __float_as_uint(jlp[k * QS + jb]);
                bl[nt][1] = __float_as_uint(jlp[(k + 4) * QS + jb]);
            }
            #pragma unroll
            for (int mt = 0; mt < 2; mt++)
                #pragma unroll
                for (int nt = 0; nt < 2; nt++) {
                    mma_tf32(acc[mt][nt], ah[mt], bh[nt]);
                    mma_tf32(acc[mt][nt], ah[mt], bl[nt]);
                    mma_tf32(acc[mt][nt], al[mt], bh[nt]);
                }
        }
        #pragma unroll
        for (int mt = 0; mt < 2; mt++) {
            #pragma unroll
            for (int hh = 0; hh < 2; hh++) {
                int idx = mt * 2 + hh;
                float v0 = acc[mt][0][hh * 2], v1 = acc[mt][0][hh * 2 + 1];
                float v2 = acc[mt][1][hh * 2], v3 = acc[mt][1][hh * 2 + 1];
                float tmax = fmaxf(fmaxf(v0, v1), fmaxf(v2, v3));
                float mnew = fmaxf(m_t[idx], tmax);
                float sc = __expf(m_t[idx] - mnew);
                float add = __expf(v0 - mnew) + __expf(v1 - mnew)
                          + __expf(v2 - mnew) + __expf(v3 - mnew);
                s_t[idx] = s_t[idx] * sc + add;
                m_t[idx] = mnew;
            }
        }
    }
    #pragma unroll
    for (int mt = 0; mt < 2; mt++)
        #pragma unroll
        for (int hh = 0; hh < 2; hh++) {
            int row = wi * 32 + mt * 16 + hh * 8 + lr;
            int slot = wj * 4 + lc;
            red_m[row * 16 + slot] = m_t[mt * 2 + hh];
            red_s[row * 16 + slot] = s_t[mt * 2 + hh];
        }
    __syncthreads();
    if (tid < 64) {
        float mt_ = -1e30f;
        #pragma unroll
        for (int k = 0; k < 16; k++) mt_ = fmaxf(mt_, red_m[tid * 16 + k]);
        float s = 0.f;
        #pragma unroll
        for (int k = 0; k < 16; k++)
            s += red_s[tid * 16 + k] * __expf(red_m[tid * 16 + k] - mt_);
        size_t p = ((size_t)jh * BB + b) * NP + i0 + tid;
        rowm_p[p] = mt_;
        rows_p[p] = s;
    }
}

// merge 4 j-quarter partials
__global__ void stats_merge_k(const float* __restrict__ mp, const float* __restrict__ sp,
                              float* __restrict__ rowm, float* __restrict__ rowsinv)
{
    int i = blockIdx.x * 256 + threadIdx.x;    // BB*NP
    float m = -1e30f;
    #pragma unroll
    for (int k = 0; k < 4; k++) m = fmaxf(m, mp[(size_t)k * BB * NP + i]);
    float s = 0.f;
    #pragma unroll
    for (int k = 0; k < 4; k++)
        s += sp[(size_t)k * BB * NP + i] * __expf(mp[(size_t)k * BB * NP + i] - m);
    rowm[i] = m;
    rowsinv[i] = 1.f / s;
}

// =====================================================================
// PASS 2: fused energy->softmax->colsum->v@attn over HALF the i-range.
// Writes partial x_r and partial colsum; combine kernel finishes.
// =====================================================================
#define FUSE_SMEM_FLOATS 28224
__global__ __launch_bounds__(256) void attn_fuse_k(
    const float* __restrict__ qhi, const float* __restrict__ qlo,
    const float* __restrict__ v,
    const float* __restrict__ rowm, const float* __restrict__ rowsinv,
    float* __restrict__ pacc, float* __restrict__ pcs)
{
    extern __shared__ __align__(16) float sm[];
    float* qjh = sm;                  // 2304
    float* qjl = sm + 2304;           // 2304
    float* qih = sm + 4608;           // [2][2304]
    float* qil = sm + 9216;           // [2][2304]
    float* v_s = sm + 13824;          // 9728 (single buffer)
    float* at_s = sm + 23552;         // [64][72]
    float* cs_s = sm + 28160;         // 64

    const int b = blockIdx.y;
    const int n0 = blockIdx.x * 64;
    const int half = blockIdx.z;      // 0/1 i-half
    const float* qhb = qhi + (size_t)b * 32 * NP;
    const float* qlb = qlo + (size_t)b * 32 * NP;
    const float* vb = v + (size_t)b * 128 * NP;
    const int tid = threadIdx.x;
    const int wid = tid >> 5, lane = tid & 31;
    const int lr = lane >> 2, lc = lane & 3;
    const int w1 = wid >> 1;
    const int w2 = wid & 1;

    if (tid < 64) cs_s[tid] = 0.f;

    const int ibase = half * 2048;
    for (int t = tid; t < 512; t += 256) {
        int r = t >> 4, s4 = (t & 15) * 4;
        cpa16(smem_u32(qjh + r * 72 + s4), qhb + (size_t)r * NP + n0 + s4);
        cpa16(smem_u32(qjl + r * 72 + s4), qlb + (size_t)r * NP + n0 + s4);
        cpa16(smem_u32(qih + r * 72 + s4), qhb + (size_t)r * NP + ibase + s4);
        cpa16(smem_u32(qil + r * 72 + s4), qlb + (size_t)r * NP + ibase + s4);
    }
    for (int t = tid; t < 2048; t += 256) {
        int r = t >> 4, s4 = (t & 15) * 4;
        cpa16(smem_u32(v_s + r * 76 + s4), vb + (size_t)r * NP + ibase + s4);
    }
    cpa_commit();

    float acc_v[2][4][4];
    #pragma unroll
    for (int a = 0; a < 2; a++)
        #pragma unroll
        for (int c = 0; c < 4; c++)
            #pragma unroll
            for (int e = 0; e < 4; e++) acc_v[a][c][e] = 0.f;
    float cs_part[8];
    #pragma unroll
    for (int p = 0; p < 8; p++) cs_part[p] = 0.f;

    for (int it = 0; it < 32; it++) {
        cpa_wait0(); __syncthreads();
        int buf = it & 1;
        const int i0 = ibase + it * 64;
        if (it + 1 < 32) {
            int i0n = i0 + 64;
            for (int t = tid; t < 512; t += 256) {
                int r = t >> 4, s4 = (t & 15) * 4;
                cpa16(smem_u32(qih + (buf ^ 1) * 2304 + r * 72 + s4), qhb + (size_t)r * NP + i0n + s4);
                cpa16(smem_u32(qil + (buf ^ 1) * 2304 + r * 72 + s4), qlb + (size_t)r * NP + i0n + s4);
            }
            cpa_commit();
        }
        const float* qiph = qih + buf * 2304;
        const float* qipl = qil + buf * 2304;

        // ---- phase e ----
        float ae[4][4];
        #pragma unroll
        for (int c = 0; c < 4; c++)
            #pragma unroll
            for (int e = 0; e < 4; e++) ae[c][e] = 0.f;
        #pragma unroll
        for (int ks = 0; ks < 4; ks++) {
            int k = ks * 8 + lc;
            int ib = w1 * 16 + lr;
            uint32_t ah[4], al[4];
            ah[0] = __float_as_uint(qiph[k * 72 + ib]);
            ah[1] = __float_as_uint(qiph[k * 72 + ib + 8]);
            ah[2] = __float_as_uint(qiph[(k + 4) * 72 + ib]);
            ah[3] = __float_as_uint(qiph[(k + 4) * 72 + ib + 8]);
            al[0] = __float_as_uint(qipl[k * 72 + ib]);
            al[1] = __float_as_uint(qipl[k * 72 + ib + 8]);
            al[2] = __float_as_uint(qipl[(k + 4) * 72 + ib]);
            al[3] = __float_as_uint(qipl[(k + 4) * 72 + ib + 8]);
            #pragma unroll
            for (int nt = 0; nt < 4; nt++) {
                int jb = w2 * 32 + nt * 8 + lr;
                uint32_t bh[2], bl[2];
                bh[0] = __float_as_uint(qjh[k * 72 + jb]);
                bh[1] = __float_as_uint(qjh[(k + 4) * 72 + jb]);
                bl[0] = __float_as_uint(qjl[k * 72 + jb]);
                bl[1] = __float_as_uint(qjl[(k + 4) * 72 + jb]);
                mma_tf32(ae[nt], ah, bh);
                mma_tf32(ae[nt], ah, bl);
                mma_tf32(ae[nt], al, bh);
            }
        }
        {
            int gi = b * NP + i0 + w1 * 16 + lr;
            float m0 = rowm[gi],     m1 = rowm[gi + 8];
            float si0 = rowsinv[gi], si1 = rowsinv[gi + 8];
            #pragma unroll
            for (int nt = 0; nt < 4; nt++) {
                float e00 = __expf(ae[nt][0] - m0) * si0;
                float e01 = __expf(ae[nt][1] - m0) * si0;
                float e10 = __expf(ae[nt][2] - m1) * si1;
                float e11 = __expf(ae[nt][3] - m1) * si1;
                int jb = w2 * 32 + nt * 8 + lc * 2;
                int ib = w1 * 16 + lr;
                *(float2*)&at_s[ib * 72 + jb] =
                    make_float2(__uint_as_float(f2tf(e00)), __uint_as_float(f2tf(e01)));
                *(float2*)&at_s[(ib + 8) * 72 + jb] =
                    make_float2(__uint_as_float(f2tf(e10)), __uint_as_float(f2tf(e11)));
                cs_part[nt * 2]     += e00 + e10;
                cs_part[nt * 2 + 1] += e01 + e11;
            }
        }
        __syncthreads();

        // ---- phase v ----
        #pragma unroll
        for (int ks = 0; ks < 8; ks++) {
            int k = ks * 8 + lc;
            uint32_t av[2][4];
            #pragma unroll
            for (int mt = 0; mt < 2; mt++) {
                int cb = w1 * 32 + mt * 16 + lr;
                av[mt][0] = __float_as_uint(v_s[cb * 76 + k]);
                av[mt][1] = __float_as_uint(v_s[(cb + 8) * 76 + k]);
                av[mt][2] = __float_as_uint(v_s[cb * 76 + k + 4]);
                av[mt][3] = __float_as_uint(v_s[(cb + 8) * 76 + k + 4]);
            }
            #pragma unroll
            for (int nt = 0; nt < 4; nt++) {
                int jb = w2 * 32 + nt * 8 + lr;
                uint32_t bv[2];
                bv[0] = __float_as_uint(at_s[k * 72 + jb]);
                bv[1] = __float_as_uint(at_s[(k + 4) * 72 + jb]);
                #pragma unroll
                for (int mt = 0; mt < 2; mt++)
                    mma_tf32(acc_v[mt][nt], av[mt], bv);
            }
        }
        __syncthreads();                       // all warps done with v_s
        if (it + 1 < 32) {                     // prefetch next v into the single buffer
            int i0n = i0 + 64;
            for (int t = tid; t < 2048; t += 256) {
                int r = t >> 4, s4 = (t & 15) * 4;
                cpa16(smem_u32(v_s + r * 76 + s4), vb + (size_t)r * NP + i0n + s4);
            }
            cpa_commit();
        }
    }

    #pragma unroll
    for (int p = 0; p < 8; p++) {
        int jb = w2 * 32 + (p >> 1) * 8 + lc * 2 + (p & 1);
        atomicAdd(&cs_s[jb], cs_part[p]);
    }
    __syncthreads();
    if (tid < 64)
        pcs[((size_t)half * BB + b) * NP + n0 + tid] = cs_s[tid];

    // store partial x_r
    #pragma unroll
    for (int mt = 0; mt < 2; mt++) {
        #pragma unroll
        for (int hh = 0; hh < 2; hh++) {
            int c = w1 * 32 + mt * 16 + hh * 8 + lr;
            #pragma unroll
            for (int nt = 0; nt < 4; nt++) {
                int jb = w2 * 32 + nt * 8 + lc * 2;
                float2 o = make_float2(acc_v[mt][nt][hh * 2], acc_v[mt][nt][hh * 2 + 1]);
                *(float2*)&pacc[(((size_t)half * BB + b) * 128 + c) * NP + n0 + jb] = o;
            }
        }
    }
}

// combine: u = h - (p0+p1)/(1e-9 + cs0+cs1)
__global__ void fuse_combine_k(const float* __restrict__ pacc, const float* __restrict__ pcs,
                               const float* __restrict__ hin, size_t sHin, float* __restrict__ u)
{
    size_t idx = (size_t)blockIdx.x * 256 + threadIdx.x;   // BB*128*NP
    int b = (int)(idx / (128 * NP));
    size_t rem = idx % ((size_t)128 * NP);
    int c = (int)(rem / NP);
    int j = (int)(rem % NP);
    float cs = pcs[(size_t)b * NP + j] + pcs[((size_t)BB + b) * NP + j];
    float xr = pacc[((size_t)b * 128 + c) * NP + j]
             + pacc[(((size_t)BB + b) * 128 + c) * NP + j];
    u[idx] = hin[(size_t)b * sHin + (size_t)c * NP + j] - xr / (1e-9f + cs);
}

// ---------------- tf32 tensor-core GEMM with fused epilogues ----------------
template<int BN>
__device__ __forceinline__ void t_load(float* As, float* Bs,
    const float* __restrict__ Ab, const float* __restrict__ Bb,
    int tid, int kt, int lda, int N)
{
    constexpr int ASTR = 20;
    constexpr int BSTR = BN + 8;
    #pragma unroll
    for (int i = 0; i < 2; i++) {
        int idx = tid + i * 256;
        int row = idx >> 2, seg = (idx & 3) * 4;
        cpa16(smem_u32(As + row * ASTR + seg), Ab + (size_t)row * lda + kt * 16 + seg);
    }
    constexpr int BF4 = BN / 64;
    #pragma unroll
    for (int i = 0; i < BF4; i++) {
        int idx = tid + i * 256;
        int row = idx / (BN / 4), seg = (idx % (BN / 4)) * 4;
        cpa16(smem_u32(Bs + row * BSTR + seg), Bb + (size_t)(kt * 16 + row) * N + seg);
    }
}

// OUT: 0 = fp32 store, 2 = tf32-rounded store
template<int BN, int ACT, int RES, int OUT>
__global__ __launch_bounds__(256) void tgemm_k(int M, int N, int K, int lda,
    const float* __restrict__ A, size_t sA,
    const float* __restrict__ B, size_t sB,
    float* __restrict__ C, size_t sC,
    const float* __restrict__ rb, size_t sRB,
    const float* __restrict__ bng, const float* __restrict__ bnb, float bninv,
    const float* __restrict__ res, size_t sRes,
    float slope)
{
    constexpr int BM = 128, BK = 16;
    constexpr int ASTR = 20;
    constexpr int BSTR = BN + 8;
    constexpr int WN = BN / 4;
    constexpr int NT = WN / 8;
    __shared__ __align__(16) float As[2][BM * ASTR];
    __shared__ __align__(16) float Bs[2][BK * BSTR];

    const int b = blockIdx.z;
    const int m0 = blockIdx.y * BM, n0 = blockIdx.x * BN;
    const float* Ab = A + (size_t)b * sA + (size_t)m0 * lda;
    const float* Bb = B + (size_t)b * sB + n0;
    const int tid = threadIdx.x;
    const int wid = tid >> 5, lane = tid & 31;
    const int wm = wid >> 2, wn = wid & 3;
    const int lr = lane >> 2, lc = lane & 3;

    float acc[4][NT][4];
    #pragma unroll
    for (int i = 0; i < 4; i++)
        #pragma unroll
        for (int j = 0; j < NT; j++)
            #pragma unroll
            for (int e = 0; e < 4; e++) acc[i][j][e] = 0.f;

    const int nk = K / BK;
    t_load<BN>(As[0], Bs[0], Ab, Bb, tid, 0, lda, N);
    cpa_commit();

    for (int kt = 0; kt < nk; kt++) {
        cpa_wait0();
        __syncthreads();
        int buf = kt & 1;
        if (kt + 1 < nk) {
            t_load<BN>(As[buf ^ 1], Bs[buf ^ 1], Ab, Bb, tid, kt + 1, lda, N);
            cpa_commit();
        }
        #pragma unroll
        for (int ks = 0; ks < 2; ks++) {
            const float* Ap = &As[buf][0];
            const float* Bp = &Bs[buf][0];
            uint32_t af[4][4];
            #pragma unroll
            for (int mt = 0; mt < 4; mt++) {
                int r = wm * 64 + mt * 16 + lr;
                int c = ks * 8 + lc;
                af[mt][0] = f2tf(Ap[(r    ) * ASTR + c    ]);
                af[mt][1] = f2tf(Ap[(r + 8) * ASTR + c    ]);
                af[mt][2] = f2tf(Ap[(r    ) * ASTR + c + 4]);
                af[mt][3] = f2tf(Ap[(r + 8) * ASTR + c + 4]);
            }
            uint32_t bf[NT][2];
            #pragma unroll
            for (int nt = 0; nt < NT; nt++) {
                int cgl = wn * WN + nt * 8 + lr;
                int k = ks * 8 + lc;
                bf[nt][0] = f2tf(Bp[(k    ) * BSTR + cgl]);
                bf[nt][1] = f2tf(Bp[(k + 4) * BSTR + cgl]);
            }
            #pragma unroll
            for (int mt = 0; mt < 4; mt++)
                #pragma unroll
                for (int nt = 0; nt < NT; nt++)
                    mma_tf32(acc[mt][nt], af[mt], bf[nt]);
        }
        __syncthreads();
    }

    #pragma unroll
    for (int mt = 0; mt < 4; mt++) {
        #pragma unroll
        for (int h = 0; h < 2; h++) {
            int mm = m0 + wm * 64 + mt * 16 + h * 8 + lr;
            float scale = (bng ? bng[mm] : 1.f) * bninv;
            float shift = bnb ? bnb[mm] : 0.f;
            float rbv   = rb  ? rb[(size_t)b * sRB + mm] : 0.f;
            #pragma unroll
            for (int nt = 0; nt < NT; nt++) {
                int n = n0 + wn * WN + nt * 8 + lc * 2;
                float v0 = acc[mt][nt][h * 2 + 0];
                float v1 = acc[mt][nt][h * 2 + 1];
                v0 = (v0 + rbv) * scale + shift;
                v1 = (v1 + rbv) * scale + shift;
                if (ACT == 1) { v0 = fmaxf(v0, 0.f); v1 = fmaxf(v1, 0.f); }
                else if (ACT == 2) { v0 = v0 > 0.f ? v0 : slope * v0; v1 = v1 > 0.f ? v1 : slope * v1; }
                if (RES == 1) {
                    v0 = res[(size_t)b * sRes + (size_t)mm * N + n] + v0;
                    v1 = res[(size_t)b * sRes + (size_t)mm * N + n + 1] + v1;
                } else if (RES == 2) {
                    v0 = res[(size_t)b * sRes + (size_t)mm * N + n] - v0;
                    v1 = res[(size_t)b * sRes + (size_t)mm * N + n + 1] - v1;
                }
                if (OUT == 2) {
                    v0 = __uint_as_float(f2tf(v0));
                    v1 = __uint_as_float(f2tf(v1));
                }
                *(float2*)&C[(size_t)b * sC + (size_t)mm * N + n] = make_float2(v0, v1);
            }
        }
    }
}

// ---------------- fp32 tiled SGEMM (q only) ----------------
template<int OMODE>
__global__ void gemm_k(int M, int N, int K, int lda,
    const float* __restrict__ A, size_t sA,
    const float* __restrict__ B, size_t sB,
    float* __restrict__ C, float* __restrict__ C2, size_t sC)
{
    __shared__ float As[16][68];
    __shared__ float Bs[16][68];
    const int b  = blockIdx.z;
    const float* Ab = A + (size_t)b * sA;
    const float* Bb = B + (size_t)b * sB;
    const int m0 = blockIdx.y * 64;
    const int n0 = blockIdx.x * 64;
    const int tid = threadIdx.x;
    const int tx = tid & 15, ty = tid >> 4;

    float acc[4][4];
    #pragma unroll
    for (int i = 0; i < 4; i++)
        #pragma unroll
        for (int j = 0; j < 4; j++) acc[i][j] = 0.f;

    for (int k0 = 0; k0 < K; k0 += 16) {
        {
            int m = tid >> 2, kq = tid & 3;
            float4 av = make_float4(0.f, 0.f, 0.f, 0.f);
            if (m0 + m < M)
                av = *(const float4*)&Ab[(size_t)(m0 + m) * lda + k0 + kq * 4];
            As[kq * 4 + 0][m] = av.x;
            As[kq * 4 + 1][m] = av.y;
            As[kq * 4 + 2][m] = av.z;
            As[kq * 4 + 3][m] = av.w;
        }
        {
            int kk = tid >> 4, nq = tid & 15;
            float4 bv = *(const float4*)&Bb[(size_t)(k0 + kk) * N + n0 + nq * 4];
            *(float4*)&Bs[kk][nq * 4] = bv;
        }
        __syncthreads();
        #pragma unroll
        for (int k = 0; k < 16; k++) {
            float4 a4 = *(float4*)&As[k][ty * 4];
            float4 b4 = *(float4*)&Bs[k][tx * 4];
            float ar[4] = {a4.x, a4.y, a4.z, a4.w};
            float br[4] = {b4.x, b4.y, b4.z, b4.w};
            #pragma unroll
            for (int i = 0; i < 4; i++)
                #pragma unroll
                for (int j = 0; j < 4; j++)
                    acc[i][j] = fmaf(ar[i], br[j], acc[i][j]);
        }
        __syncthreads();
    }

    #pragma unroll
    for (int i = 0; i < 4; i++) {
        int m = m0 + ty * 4 + i;
        if (m >= M) continue;
        #pragma unroll
        for (int j = 0; j < 4; j++) {
            int n = n0 + tx * 4 + j;
            float v = acc[i][j];
            size_t off = (size_t)b * sC + (size_t)m * N + n;
            if (OMODE == 1) {
                uint32_t hi, lo; split_tf(v, hi, lo);
                C[off]  = __uint_as_float(hi);
                C2[off] = __uint_as_float(lo);
            } else {
                C[off] = v;
            }
        }
    }
}

// ---------------- conv1 ----------------
__global__ void conv1_k(const float* __restrict__ x, const float* __restrict__ w1,
                        const float* __restrict__ g, const float* __restrict__ bb,
                        float inv, float* __restrict__ out)
{
    int idx = blockIdx.x * blockDim.x + threadIdx.x;
    int n = idx & (NP - 1);
    int o = (idx / NP) & 127;
    int b = idx / (128 * NP);
    const float* xp = x + ((size_t)b * 15 + 9) * NP + n;
    float s = w1[o * 3 + 0] * xp[0] + w1[o * 3 + 1] * xp[NP] + w1[o * 3 + 2] * xp[2 * NP];
    s = s * g[o] * inv + bb[o];
    out[idx] = fmaxf(s, 0.f);
}

// ---------------- global max/mean pooling over N ----------------
__global__ void pool_k(const float* __restrict__ hf, float* __restrict__ xmax, float* __restrict__ xavg)
{
    int bc = blockIdx.x;
    const float* p = hf + (size_t)bc * NP;
    int t = threadIdx.x;
    float mx = -1e30f, sm = 0.f;
    for (int i = t; i < NP; i += 256) { float v = p[i]; mx = fmaxf(mx, v); sm += v; }
    __shared__ float rm[256], rs[256];
    rm[t] = mx; rs[t] = sm; __syncthreads();
    for (int s = 128; s > 0; s >>= 1) {
        if (t < s) { rm[t] = fmaxf(rm[t], rm[t + s]); rs[t] += rs[t + s]; }
        __syncthreads();
    }
    if (t == 0) { xmax[bc] = rm[0]; xavg[bc] = rs[0] * (1.f / NP); }
}

// ---------------- fold pooled channels of ws1 into per-row bias ----------------
__global__ void r1_k(const float* __restrict__ ws1, const float* __restrict__ bs1,
                     const float* __restrict__ xmax, const float* __restrict__ xavg,
                     float* __restrict__ r1)
{
    int idx = blockIdx.x * blockDim.x + threadIdx.x;
    if (idx >= BB * 512) return;
    int b = idx / 512, o = idx % 512;
    const float* w = ws1 + (size_t)o * 3072;
    float s = bs1[o];
    #pragma unroll 4
    for (int c = 0; c < 1024; c++)
        s += w[1024 + c] * xmax[b * 1024 + c] + w[2048 + c] * xavg[b * 1024 + c];
    r1[idx] = s;
}

// ---------------- ws3 (8x256) + log_softmax + transpose ----------------
__global__ void final_k(const float* __restrict__ s2, const float* __restrict__ ws3,
                        const float* __restrict__ bs3, float* __restrict__ out)
{
    __shared__ float w[8 * 256];
    __shared__ float bias[8];
    int t = threadIdx.x;
    for (int i = t; i < 2048; i += blockDim.x) w[i] = ws3[i];
    if (t < 8) bias[t] = bs3[t];
    __syncthreads();
    int idx = blockIdx.x * blockDim.x + t;
    int b = idx / NP, n = idx & (NP - 1);
    const float* sp = s2 + (size_t)b * 256 * NP + n;
    float l[8];
    #pragma unroll
    for (int k = 0; k < 8; k++) l[k] = bias[k];
    for (int c = 0; c < 256; c++) {
        float v = sp[(size_t)c * NP];
        #pragma unroll
        for (int k = 0; k < 8; k++) l[k] = fmaf(w[k * 256 + c], v, l[k]);
    }
    float m = l[0];
    #pragma unroll
    for (int k = 1; k < 8; k++) m = fmaxf(m, l[k]);
    float s = 0.f;
    #pragma unroll
    for (int k = 0; k < 8; k++) s += expf(l[k] - m);
    float lse = m + logf(s);
    #pragma unroll
    for (int k = 0; k < 8; k++)
        out[((size_t)b * NP + n) * 8 + k] = l[k] - lse;
}

// ---------------- host launch ----------------
extern "C" void kernel_launch(void* const* d_in, const int* in_sizes, int n_in,
                              void* d_out, int out_size)
{
    const float* x      = (const float*)d_in[0];
    const float* w1     = (const float*)d_in[1];
    const float* bn1_g  = (const float*)d_in[2];
    const float* bn1_b  = (const float*)d_in[3];
    const float* w2     = (const float*)d_in[4];
    const float* bn2_g  = (const float*)d_in[5];
    const float* bn2_b  = (const float*)d_in[6];
    const float* sa_wqk = (const float*)d_in[7];
    const float* sa_wv  = (const float*)d_in[8];
    const float* sa_bv  = (const float*)d_in[9];
    const float* sa_wt  = (const float*)d_in[10];
    const float* sa_bt  = (const float*)d_in[11];
    const float* sa_bng = (const float*)d_in[12];
    const float* sa_bnb = (const float*)d_in[13];
    const float* wf     = (const float*)d_in[14];
    const float* bnf_g  = (const float*)d_in[15];
    const float* bnf_b  = (const float*)d_in[16];
    const float* ws1    = (const float*)d_in[17];
    const float* bs1    = (const float*)d_in[18];
    const float* bns1_g = (const float*)d_in[19];
    const float* bns1_b = (const float*)d_in[20];
    const float* ws2    = (const float*)d_in[21];
    const float* bs2    = (const float*)d_in[22];
    const float* bns2_g = (const float*)d_in[23];
    const float* bns2_b = (const float*)d_in[24];
    const float* ws3    = (const float*)d_in[25];
    const float* bs3    = (const float*)d_in[26];
    float* out = (float*)d_out;

    float *c1, *h0, *qhi, *qlo, *v, *u, *rowm, *rowsinv, *rowm_p, *rows_p, *pacc, *pcs;
    float *feats, *hf, *xmax, *xavg, *r1, *s1, *s2;
    cudaGetSymbolAddress((void**)&c1,      g_c1);
    cudaGetSymbolAddress((void**)&h0,      g_h0);
    cudaGetSymbolAddress((void**)&qhi,     g_qhi);
    cudaGetSymbolAddress((void**)&qlo,     g_qlo);
    cudaGetSymbolAddress((void**)&v,       g_v);
    cudaGetSymbolAddress((void**)&u,       g_u);
    cudaGetSymbolAddress((void**)&rowm,    g_rowm);
    cudaGetSymbolAddress((void**)&rowsinv, g_rowsinv);
    cudaGetSymbolAddress((void**)&rowm_p,  g_rowm_p);
    cudaGetSymbolAddress((void**)&rows_p,  g_rows_p);
    cudaGetSymbolAddress((void**)&pacc,    g_pacc);
    cudaGetSymbolAddress((void**)&pcs,     g_pcs);
    cudaGetSymbolAddress((void**)&feats,   g_feats);
    cudaGetSymbolAddress((void**)&hf,      g_hf);
    cudaGetSymbolAddress((void**)&xmax,    g_xmax);
    cudaGetSymbolAddress((void**)&xavg,    g_xavg);
    cudaGetSymbolAddress((void**)&r1,      g_r1);
    cudaGetSymbolAddress((void**)&s1,      g_s1);
    cudaGetSymbolAddress((void**)&s2,      g_s2);

    const float INV = 0.999995000037499219f;   // 1/sqrt(1 + 1e-5)
    dim3 blk(256);
    const int STATS_SMEM = STATS_SMEM_FLOATS * 4;
    const int FUSE_SMEM  = FUSE_SMEM_FLOATS * 4;
    cudaFuncSetAttribute(attn_stats_k, cudaFuncAttributeMaxDynamicSharedMemorySize, STATS_SMEM);
    cudaFuncSetAttribute(attn_fuse_k,  cudaFuncAttributeMaxDynamicSharedMemorySize, FUSE_SMEM);

    // conv1: 3 -> 128, bn+relu
    conv1_k<<<(BB * 128 * NP) / 256, blk>>>(x, w1, bn1_g, bn1_b, INV, c1);

    // conv2: 128 -> 128, bn+relu  [tf32 tensor]
    tgemm_k<64,1,0,0><<<dim3(NP/64, 1, BB), blk>>>(128, NP, 128, 128,
        w2, 0, c1, (size_t)128*NP, h0, (size_t)128*NP,
        nullptr, 0, bn2_g, bn2_b, INV, nullptr, 0, 0.f);

    for (int i = 0; i < 4; i++) {
        const float* hin = (i == 0) ? h0 : feats + (size_t)(i - 1) * 128 * NP;
        size_t sHin = (i == 0) ? (size_t)128 * NP : (size_t)512 * NP;

        // q = wqk @ h  (32 x 4096) fp32 -> pre-split tf32 hi/lo
        gemm_k<1><<<dim3(NP/64, 1, BB), blk>>>(32, NP, 128, 128,
            sa_wqk + (size_t)i*32*128, 0, hin, sHin, qhi, qlo, (size_t)32*NP);

        // pass 1: row softmax stats (4 j-quarters) + merge
        attn_stats_k<<<dim3(NP/64, BB, 4), blk, STATS_SMEM>>>(qhi, qlo, rowm_p, rows_p);
        stats_merge_k<<<(BB * NP) / 256, blk>>>(rowm_p, rows_p, rowm, rowsinv);

        // v = wv @ h + bv, tf32-rounded out  [tf32 tensor]
        tgemm_k<64,0,0,2><<<dim3(NP/64, 1, BB), blk>>>(128, NP, 128, 128,
            sa_wv + (size_t)i*128*128, 0, hin, sHin, v, (size_t)128*NP,
            sa_bv + (size_t)i*128, 0, nullptr, nullptr, 1.f, nullptr, 0, 0.f);

        // pass 2: fused attention over i-halves -> partials, then combine
        attn_fuse_k<<<dim3(NP/64, BB, 2), blk, FUSE_SMEM>>>(qhi, qlo, v, rowm, rowsinv, pacc, pcs);
        fuse_combine_k<<<(BB * 128 * NP) / 256, blk>>>(pacc, pcs, hin, sHin, u);

        // h_new = h + relu(bn(wt @ u + bt))  [tf32 tensor]
        tgemm_k<64,1,1,0><<<dim3(NP/64, 1, BB), blk>>>(128, NP, 128, 128,
            sa_wt + (size_t)i*128*128, 0, u, (size_t)128*NP,
            feats + (size_t)i*128*NP, (size_t)512*NP,
            sa_bt + (size_t)i*128, 0, sa_bng + (size_t)i*128, sa_bnb + (size_t)i*128, INV,
            hin, sHin, 0.f);
    }

    // wf: 512 -> 1024, bn + leaky_relu(0.2)  [tf32 tensor]
    tgemm_k<128,2,0,0><<<dim3(NP/128, 1024/128, BB), blk>>>(1024, NP, 512, 512,
        wf, 0, feats, (size_t)512*NP, hf, (size_t)1024*NP,
        nullptr, 0, bnf_g, bnf_b, INV, nullptr, 0, 0.2f);

    pool_k<<<BB * 1024, blk>>>(hf, xmax, xavg);
    r1_k<<<(BB * 512 + 255) / 256, blk>>>(ws1, bs1, xmax, xavg, r1);

    // ws1 (first 1024 input channels of 3072; pooled part folded into r1)  [tf32]
    tgemm_k<128,1,0,0><<<dim3(NP/128, 512/128, BB), blk>>>(512, NP, 1024, 3072,
        ws1, 0, hf, (size_t)1024*NP, s1, (size_t)512*NP,
        r1, 512, bns1_g, bns1_b, INV, nullptr, 0, 0.f);

    // ws2: 512 -> 256, bn + relu  [tf32]
    tgemm_k<128,1,0,0><<<dim3(NP/128, 256/128, BB), blk>>>(256, NP, 512, 512,
        ws2, 0, s1, (size_t)512*NP, s2, (size_t)256*NP,
        bs2, 0, bns2_g, bns2_b, INV, nullptr, 0, 0.f);

    // ws3 + log_softmax + transpose
    final_k<<<(BB * NP) / 256, blk>>>(s2, ws3, bs3, out);
}